// round 2
// baseline (speedup 1.0000x reference)
#include <cuda_runtime.h>
#include <cuda_fp16.h>
#include <math.h>

// Problem constants
#define Bn 8
#define Ln 4096
#define Hn 1024
#define Nn 32
#define Tn 128            // chunk length
#define Cc 32             // chunks (Tn*Cc == Ln)
#define BC 256            // B*C columns
#define KD 192            // main GEMM K dim: 128 (u) + 64 (states)

// ---- persistent device buffers (no allocs allowed) ----
__device__ __half  g_M[Hn * Tn * KD];        // per-h [Toep(128) | Dec(64)] : [128][192] fp16
__device__ __half  g_Enc[Hn * 64 * Tn];      // per-h Enc [64][128] fp16
__device__ __half  g_V[(size_t)Hn * BC * KD];// per-h B operand [256][192] fp16 (u | states)
__device__ float   g_Xl[Hn * 64 * BC];       // per-h local states [64][256] fp32
__device__ float   g_yT[(size_t)Hn * BC * Tn];// per-h output [256][128] fp32
__device__ float2  g_wT[Hn * Nn];            // w^T per (h,n)

// ---- small helpers ----
static __device__ __forceinline__ unsigned smem_u32(const void* p) {
    unsigned r;
    asm("{ .reg .u64 t; cvta.to.shared.u64 t, %1; cvt.u32.u64 %0, t; }"
        : "=r"(r) : "l"(p));
    return r;
}
static __device__ __forceinline__ void ldmA(unsigned addr, unsigned& r0, unsigned& r1,
                                            unsigned& r2, unsigned& r3) {
    asm volatile("ldmatrix.sync.aligned.m8n8.x4.shared.b16 {%0,%1,%2,%3}, [%4];"
                 : "=r"(r0), "=r"(r1), "=r"(r2), "=r"(r3) : "r"(addr));
}
static __device__ __forceinline__ void ldmB(unsigned addr, unsigned& r0, unsigned& r1) {
    asm volatile("ldmatrix.sync.aligned.m8n8.x2.shared.b16 {%0,%1}, [%2];"
                 : "=r"(r0), "=r"(r1) : "r"(addr));
}
static __device__ __forceinline__ void mma16816(float* d, const unsigned* a,
                                                const unsigned* b) {
    asm volatile(
        "mma.sync.aligned.m16n8k16.row.col.f32.f16.f16.f32 "
        "{%0,%1,%2,%3}, {%4,%5,%6,%7}, {%8,%9}, {%0,%1,%2,%3};"
        : "+f"(d[0]), "+f"(d[1]), "+f"(d[2]), "+f"(d[3])
        : "r"(a[0]), "r"(a[1]), "r"(a[2]), "r"(a[3]), "r"(b[0]), "r"(b[1]));
}
static __device__ __forceinline__ float gelu_erf(float v) {
    return 0.5f * v * (1.0f + erff(v * 0.70710678118654752440f));
}

// =====================================================================
// k_tables: per-h coefficient tables in fp64 (block = one h)
//   w = exp(dt*A), C' = C*(w-1)/A
//   K[s] = 2Re(sum_n C'_n w^s)
//   Enc[n][j]   = Re(w^{127-j}), Enc[n+32][j] = Im(w^{127-j})
//   Dec[i][n]   = 2Re(C' w^{i+1}), Dec[i][n+32] = -2Im(C' w^{i+1})
//   M = [Toeplitz(K) | Dec], wT = w^128
// =====================================================================
__global__ void k_tables(const float* __restrict__ log_dt,
                         const float* __restrict__ A_real,
                         const float* __restrict__ A_imag,
                         const float* __restrict__ C_real,
                         const float* __restrict__ C_imag) {
    int h = blockIdx.x;
    int tid = threadIdx.x;
    __shared__ float Ks[Tn];

    if (tid < 32) {
        int n = tid;
        int idx = h * Nn + n;
        double dt = exp((double)log_dt[h]);
        double Ar = -exp((double)A_real[idx]);
        double Ai = (double)A_imag[idx];
        double ar = Ar * dt, ai = Ai * dt;
        double er = exp(ar);
        double wr = er * cos(ai), wi = er * sin(ai);

        double den = Ar * Ar + Ai * Ai;
        double e1r = wr - 1.0, e1i = wi;
        double qr = (e1r * Ar + e1i * Ai) / den;
        double qi = (e1i * Ar - e1r * Ai) / den;
        double Cr = (double)C_real[idx], Ci = (double)C_imag[idx];
        double cr = Cr * qr - Ci * qi;
        double ci = Cr * qi + Ci * qr;

        // wT = w^128 via 7 squarings
        double sr = wr, si = wi;
        for (int k = 0; k < 7; k++) {
            double nr = sr * sr - si * si, ni = 2.0 * sr * si;
            sr = nr; si = ni;
        }
        g_wT[h * Nn + n] = make_float2((float)sr, (float)si);

        // Enc rows
        {
            double pr = 1.0, pi = 0.0;
            __half* encR = g_Enc + (size_t)(h * 64 + n) * Tn;
            __half* encI = g_Enc + (size_t)(h * 64 + 32 + n) * Tn;
            for (int s = 0; s < Tn; s++) {
                int j = Tn - 1 - s;
                encR[j] = __float2half((float)pr);
                encI[j] = __float2half((float)pi);
                double nr = pr * wr - pi * wi, ni = pr * wi + pi * wr;
                pr = nr; pi = ni;
            }
        }
        // Dec columns of M
        {
            double dr = cr * wr - ci * wi, di = cr * wi + ci * wr; // C'*w^1
            for (int i = 0; i < Tn; i++) {
                size_t row = (size_t)(h * Tn + i) * KD;
                g_M[row + 128 + n] = __float2half((float)(2.0 * dr));
                g_M[row + 160 + n] = __float2half((float)(-2.0 * di));
                double nr = dr * wr - di * wi, ni = dr * wi + di * wr;
                dr = nr; di = ni;
            }
        }
        // K[s]
        {
            double kr = cr, ki = ci;
            for (int s = 0; s < Tn; s++) {
                float term = (float)(2.0 * kr);
#pragma unroll
                for (int off = 16; off; off >>= 1)
                    term += __shfl_xor_sync(0xffffffffu, term, off);
                if (n == 0) Ks[s] = term;
                double nr = kr * wr - ki * wi, ni = kr * wi + ki * wr;
                kr = nr; ki = ni;
            }
        }
    }
    __syncthreads();
    // Toeplitz fill
    for (int idx = tid; idx < Tn * Tn; idx += 256) {
        int i = idx >> 7, j = idx & 127;
        float v = (i >= j) ? Ks[i - j] : 0.f;
        g_M[(size_t)(h * Tn + i) * KD + j] = __float2half(v);
    }
}

// =====================================================================
// k_transpose: u (b,l,h) fp32 -> V[h][bc][0..128) fp16
// block: (h-tile 32, c, b); 256 threads
// =====================================================================
__global__ void __launch_bounds__(256)
k_transpose(const float* __restrict__ u) {
    int ht = blockIdx.x, c = blockIdx.y, b = blockIdx.z;
    __shared__ __half ts[32][136];  // [h][j], padded
    int lane = threadIdx.x & 31;    // h within tile
    int r = threadIdx.x >> 5;       // j-subrow

    const float* up = u + ((size_t)b * Ln + (size_t)c * Tn) * Hn + ht * 32;
#pragma unroll
    for (int j0 = 0; j0 < Tn; j0 += 8) {
        int j = j0 + r;
        ts[lane][j] = __float2half(up[(size_t)j * Hn + lane]);
    }
    __syncthreads();

    int row = threadIdx.x >> 3;   // h row 0..31
    int ch = threadIdx.x & 7;     // uint4 chunk
    int bc = b * Cc + c;
    __half* dst = g_V + ((size_t)(ht * 32 + row) * BC + bc) * KD;
    reinterpret_cast<uint4*>(dst)[ch] =
        *reinterpret_cast<const uint4*>(&ts[row][ch * 8]);
    reinterpret_cast<uint4*>(dst)[ch + 8] =
        *reinterpret_cast<const uint4*>(&ts[row][(ch + 8) * 8]);
}

// =====================================================================
// k_encode: per-h GEMM  Xl[64,256] = Enc[64,128] @ V_u[256,128]^T
// block per h; 8 warps as 2(m) x 4(n); warp tile 32x64
// =====================================================================
#define LDA1 136
#define LDB1 136
__global__ void __launch_bounds__(256)
k_encode() {
    int h = blockIdx.x;
    int tid = threadIdx.x;
    extern __shared__ __half sm1[];
    __half* As = sm1;                    // [64][LDA1]
    __half* Bs = sm1 + 64 * LDA1;        // [256][LDB1]

    // load A: 64 rows x 128 halves (16 uint4/row)
    {
        const uint4* src = reinterpret_cast<const uint4*>(g_Enc + (size_t)h * 64 * Tn);
        for (int i = tid; i < 64 * 16; i += 256) {
            int row = i >> 4, ch = i & 15;
            *reinterpret_cast<uint4*>(&As[row * LDA1 + ch * 8]) = src[row * 16 + ch];
        }
    }
    // load B: 256 rows x first 128 halves of V rows (stride KD)
    {
        const __half* vb = g_V + (size_t)h * BC * KD;
        for (int i = tid; i < 256 * 16; i += 256) {
            int row = i >> 4, ch = i & 15;
            *reinterpret_cast<uint4*>(&Bs[row * LDB1 + ch * 8]) =
                *reinterpret_cast<const uint4*>(&vb[(size_t)row * KD + ch * 8]);
        }
    }
    __syncthreads();

    int wid = tid >> 5, lane = tid & 31;
    int wm = wid & 1, wn = wid >> 1;
    int m_base = wm * 32, n_base = wn * 64;

    float acc[2][8][4];
#pragma unroll
    for (int a = 0; a < 2; a++)
#pragma unroll
        for (int bI = 0; bI < 8; bI++)
#pragma unroll
            for (int cI = 0; cI < 4; cI++) acc[a][bI][cI] = 0.f;

    int la = lane & 15;
    int aRowOff = (lane < 16) ? lane : (lane - 16);
    int aColOff = (lane < 16) ? 0 : 8;
    int bRowOff = la & 7;
    int bColOff = (la >> 3) * 8;

    for (int kk = 0; kk < 128; kk += 16) {
        unsigned af[2][4];
#pragma unroll
        for (int mf = 0; mf < 2; mf++) {
            int m0 = m_base + mf * 16;
            unsigned addr = smem_u32(&As[(m0 + aRowOff) * LDA1 + kk + aColOff]);
            ldmA(addr, af[mf][0], af[mf][1], af[mf][2], af[mf][3]);
        }
        unsigned bf[8][2];
#pragma unroll
        for (int nf = 0; nf < 8; nf++) {
            int n0 = n_base + nf * 8;
            unsigned addr = smem_u32(&Bs[(n0 + bRowOff) * LDB1 + kk + bColOff]);
            ldmB(addr, bf[nf][0], bf[nf][1]);
        }
#pragma unroll
        for (int mf = 0; mf < 2; mf++)
#pragma unroll
            for (int nf = 0; nf < 8; nf++)
                mma16816(acc[mf][nf], af[mf], bf[nf]);
    }

    // store Xl[h][m][n] (n contiguous) as float2
    int r = lane >> 2, cp = lane & 3;
    float* xl = g_Xl + (size_t)h * 64 * BC;
#pragma unroll
    for (int mf = 0; mf < 2; mf++) {
#pragma unroll
        for (int nf = 0; nf < 8; nf++) {
            int m = m_base + mf * 16 + r;
            int n = n_base + nf * 8 + cp * 2;
            *reinterpret_cast<float2*>(&xl[(size_t)m * BC + n]) =
                make_float2(acc[mf][nf][0], acc[mf][nf][1]);
            *reinterpret_cast<float2*>(&xl[(size_t)(m + 8) * BC + n]) =
                make_float2(acc[mf][nf][2], acc[mf][nf][3]);
        }
    }
}

// =====================================================================
// k_combine: sequential over chunks per (h,n,b); writes carry-in states
// (fp16) into V rows [128..192)
// =====================================================================
__global__ void k_combine() {
    int t = blockIdx.x * 256 + threadIdx.x;
    int n = t & 31, b = (t >> 5) & 7, h = t >> 8;

    float2 wT = g_wT[h * Nn + n];
    float XR = 0.f, XI = 0.f;
    const float* xlR = g_Xl + (size_t)h * 64 * BC + (size_t)n * BC;
    const float* xlI = xlR + 32 * BC;
    __half* vbase = g_V + (size_t)h * BC * KD;

    for (int c = 0; c < Cc; c++) {
        int bc = b * Cc + c;
        vbase[(size_t)bc * KD + 128 + n] = __float2half(XR);
        vbase[(size_t)bc * KD + 160 + n] = __float2half(XI);
        float lr = xlR[bc], li = xlI[bc];
        float nR = wT.x * XR - wT.y * XI + lr;
        float nI = wT.x * XI + wT.y * XR + li;
        XR = nR; XI = nI;
    }
}

// =====================================================================
// k_main: per-h GEMM  Y[128,256] = M[128,192] @ V[256,192]^T
// block per h; 8 warps as 2(m) x 4(n); warp tile 64x64
// =====================================================================
#define LDA2 200
#define LDB2 200
__global__ void __launch_bounds__(256)
k_main() {
    int h = blockIdx.x;
    int tid = threadIdx.x;
    extern __shared__ __half sm2[];
    __half* As = sm2;                     // [128][LDA2]
    __half* Bs = sm2 + 128 * LDA2;        // [256][LDB2]

    // load A: 128 rows x 192 halves (24 uint4/row)
    {
        const uint4* src = reinterpret_cast<const uint4*>(g_M + (size_t)h * Tn * KD);
        for (int i = tid; i < 128 * 24; i += 256) {
            int row = i / 24, ch = i % 24;
            *reinterpret_cast<uint4*>(&As[row * LDA2 + ch * 8]) = src[row * 24 + ch];
        }
    }
    // load B: 256 rows x 192 halves
    {
        const uint4* src = reinterpret_cast<const uint4*>(g_V + (size_t)h * BC * KD);
        for (int i = tid; i < 256 * 24; i += 256) {
            int row = i / 24, ch = i % 24;
            *reinterpret_cast<uint4*>(&Bs[row * LDB2 + ch * 8]) = src[row * 24 + ch];
        }
    }
    __syncthreads();

    int wid = tid >> 5, lane = tid & 31;
    int wm = wid & 1, wn = wid >> 1;
    int m_base = wm * 64, n_base = wn * 64;

    float acc[4][8][4];
#pragma unroll
    for (int a = 0; a < 4; a++)
#pragma unroll
        for (int bI = 0; bI < 8; bI++)
#pragma unroll
            for (int cI = 0; cI < 4; cI++) acc[a][bI][cI] = 0.f;

    int la = lane & 15;
    int aRowOff = (lane < 16) ? lane : (lane - 16);
    int aColOff = (lane < 16) ? 0 : 8;
    int bRowOff = la & 7;
    int bColOff = (la >> 3) * 8;

    for (int kk = 0; kk < KD; kk += 16) {
        unsigned af[4][4];
#pragma unroll
        for (int mf = 0; mf < 4; mf++) {
            int m0 = m_base + mf * 16;
            unsigned addr = smem_u32(&As[(m0 + aRowOff) * LDA2 + kk + aColOff]);
            ldmA(addr, af[mf][0], af[mf][1], af[mf][2], af[mf][3]);
        }
        unsigned bf[8][2];
#pragma unroll
        for (int nf = 0; nf < 8; nf++) {
            int n0 = n_base + nf * 8;
            unsigned addr = smem_u32(&Bs[(n0 + bRowOff) * LDB2 + kk + bColOff]);
            ldmB(addr, bf[nf][0], bf[nf][1]);
        }
#pragma unroll
        for (int mf = 0; mf < 4; mf++)
#pragma unroll
            for (int nf = 0; nf < 8; nf++)
                mma16816(acc[mf][nf], af[mf], bf[nf]);
    }

    // store yT[h][bc=n][i=m] (scalar stores)
    int r = lane >> 2, cp = lane & 3;
    float* yt = g_yT + (size_t)h * BC * Tn;
#pragma unroll
    for (int mf = 0; mf < 4; mf++) {
#pragma unroll
        for (int nf = 0; nf < 8; nf++) {
            int m = m_base + mf * 16 + r;
            int n = n_base + nf * 8 + cp * 2;
            yt[(size_t)n * Tn + m]           = acc[mf][nf][0];
            yt[(size_t)(n + 1) * Tn + m]     = acc[mf][nf][1];
            yt[(size_t)n * Tn + m + 8]       = acc[mf][nf][2];
            yt[(size_t)(n + 1) * Tn + m + 8] = acc[mf][nf][3];
        }
    }
}

// =====================================================================
// k_final: transpose yT back to (b,l,h), + D*u, erf-GELU
// block: (h-tile 32, c, b); 256 threads
// =====================================================================
__global__ void __launch_bounds__(256)
k_final(const float* __restrict__ u, const float* __restrict__ Dp,
        float* __restrict__ out) {
    int ht = blockIdx.x, c = blockIdx.y, b = blockIdx.z;
    __shared__ float ys[128][33];   // [i][h]
    int bc = b * Cc + c;

    {
        int row = threadIdx.x >> 3;   // h 0..31
        int ch = threadIdx.x & 7;
        const float4* src = reinterpret_cast<const float4*>(
            g_yT + ((size_t)(ht * 32 + row) * BC + bc) * Tn);
#pragma unroll
        for (int q = 0; q < 4; q++) {
            int chunk = ch + q * 8;           // 0..31, each 4 floats
            float4 v = src[chunk];
            int i = chunk * 4;
            ys[i + 0][row] = v.x;
            ys[i + 1][row] = v.y;
            ys[i + 2][row] = v.z;
            ys[i + 3][row] = v.w;
        }
    }
    __syncthreads();

    float Dv = *Dp;
    int lane = threadIdx.x & 31;   // h
    int r = threadIdx.x >> 5;
#pragma unroll
    for (int i0 = 0; i0 < Tn; i0 += 8) {
        int i = i0 + r;
        size_t gidx = ((size_t)b * Ln + (size_t)c * Tn + i) * Hn + ht * 32 + lane;
        float v = ys[i][lane] + Dv * u[gidx];
        out[gidx] = gelu_erf(v);
    }
}

// =====================================================================
// launch
// =====================================================================
extern "C" void kernel_launch(void* const* d_in, const int* in_sizes, int n_in,
                              void* d_out, int out_size) {
    (void)in_sizes; (void)n_in; (void)out_size;
    const float* u      = (const float*)d_in[0];
    const float* log_dt = (const float*)d_in[1];
    const float* A_real = (const float*)d_in[2];
    const float* A_imag = (const float*)d_in[3];
    const float* C_real = (const float*)d_in[4];
    const float* C_imag = (const float*)d_in[5];
    const float* D      = (const float*)d_in[6];
    float* out = (float*)d_out;

    static bool attr_done = false;
    if (!attr_done) {
        cudaFuncSetAttribute(k_encode, cudaFuncAttributeMaxDynamicSharedMemorySize,
                             (64 * LDA1 + 256 * LDB1) * 2);
        cudaFuncSetAttribute(k_main, cudaFuncAttributeMaxDynamicSharedMemorySize,
                             (128 * LDA2 + 256 * LDB2) * 2);
        attr_done = true;
    }

    k_tables<<<Hn, 256>>>(log_dt, A_real, A_imag, C_real, C_imag);
    k_transpose<<<dim3(Hn / 32, Cc, Bn), 256>>>(u);
    k_encode<<<Hn, 256, (64 * LDA1 + 256 * LDB1) * 2>>>();
    k_combine<<<(Hn * Nn * Bn) / 256, 256>>>();
    k_main<<<Hn, 256, (128 * LDA2 + 256 * LDB2) * 2>>>();
    k_final<<<dim3(Hn / 32, Cc, Bn), 256>>>(u, D, out);
}

// round 3
// speedup vs baseline: 1.8969x; 1.8969x over previous
#include <cuda_runtime.h>
#include <cuda_fp16.h>
#include <math.h>

// Problem constants
#define Bn 8
#define Ln 4096
#define Hn 1024
#define Nn 32
#define Tn 128            // chunk length
#define Cc 32             // chunks (Tn*Cc == Ln)
#define BC 256            // B*C columns
#define KD 192            // main GEMM K dim: 128 (u) + 64 (states)

// ---- persistent device buffers (no allocs allowed) ----
__device__ __align__(256) __half  g_M[Hn * Tn * KD];         // per-h [Toep|Dec] [128][192]
__device__ __align__(256) __half  g_Enc[Hn * 64 * Tn];       // per-h Enc [64][128]
__device__ __align__(256) __half  g_V[(size_t)Hn * BC * KD]; // per-h B op [256][192] (u|states)
__device__ __align__(256) float   g_yT[(size_t)Hn * BC * Tn];// per-h output [256][128]
__device__ __align__(256) float2  g_wT[Hn * Nn];             // w^T per (h,n)

// ---- small helpers ----
static __device__ __forceinline__ unsigned smem_u32(const void* p) {
    unsigned r;
    asm("{ .reg .u64 t; cvta.to.shared.u64 t, %1; cvt.u32.u64 %0, t; }"
        : "=r"(r) : "l"(p));
    return r;
}
static __device__ __forceinline__ void ldmA(unsigned addr, unsigned& r0, unsigned& r1,
                                            unsigned& r2, unsigned& r3) {
    asm volatile("ldmatrix.sync.aligned.m8n8.x4.shared.b16 {%0,%1,%2,%3}, [%4];"
                 : "=r"(r0), "=r"(r1), "=r"(r2), "=r"(r3) : "r"(addr));
}
static __device__ __forceinline__ void ldmB(unsigned addr, unsigned& r0, unsigned& r1) {
    asm volatile("ldmatrix.sync.aligned.m8n8.x2.shared.b16 {%0,%1}, [%2];"
                 : "=r"(r0), "=r"(r1) : "r"(addr));
}
static __device__ __forceinline__ void mma16816(float* d, const unsigned* a,
                                                const unsigned* b) {
    asm volatile(
        "mma.sync.aligned.m16n8k16.row.col.f32.f16.f16.f32 "
        "{%0,%1,%2,%3}, {%4,%5,%6,%7}, {%8,%9}, {%0,%1,%2,%3};"
        : "+f"(d[0]), "+f"(d[1]), "+f"(d[2]), "+f"(d[3])
        : "r"(a[0]), "r"(a[1]), "r"(a[2]), "r"(a[3]), "r"(b[0]), "r"(b[1]));
}
static __device__ __forceinline__ float gelu_erf(float v) {
    return 0.5f * v * (1.0f + erff(v * 0.70710678118654752440f));
}

// =====================================================================
// k_tables (fp32): per-h coefficient tables
//   w = exp(dt*A), C' = C*(w-1)/A
//   K[s] = 2Re(sum_n C'_n w^s)
//   Enc[n][j]   = Re(w^{127-j}), Enc[n+32][j] = Im(w^{127-j})
//   Dec[i][n]   = 2Re(C' w^{i+1}), Dec[i][n+32] = -2Im(C' w^{i+1})
//   M = [Toeplitz(K) | Dec], wT = w^128
// =====================================================================
__global__ void k_tables(const float* __restrict__ log_dt,
                         const float* __restrict__ A_real,
                         const float* __restrict__ A_imag,
                         const float* __restrict__ C_real,
                         const float* __restrict__ C_imag) {
    int h = blockIdx.x;
    int tid = threadIdx.x;
    __shared__ float Ks[Tn];

    if (tid < 32) {
        int n = tid;
        int idx = h * Nn + n;
        float dt = expf(log_dt[h]);
        float Ar = -expf(A_real[idx]);
        float Ai = A_imag[idx];
        float ar = Ar * dt, ai = Ai * dt;
        float er = expf(ar);
        float sn, cs;
        sincosf(ai, &sn, &cs);
        float wr = er * cs, wi = er * sn;

        float den = Ar * Ar + Ai * Ai;
        float e1r = wr - 1.0f, e1i = wi;
        float qr = (e1r * Ar + e1i * Ai) / den;
        float qi = (e1i * Ar - e1r * Ai) / den;
        float Cr = C_real[idx], Ci = C_imag[idx];
        float cr = Cr * qr - Ci * qi;
        float ci = Cr * qi + Ci * qr;

        // wT = w^128 via 7 squarings
        {
            float sr = wr, si = wi;
#pragma unroll
            for (int k = 0; k < 7; k++) {
                float nr = sr * sr - si * si, ni = 2.0f * sr * si;
                sr = nr; si = ni;
            }
            g_wT[h * Nn + n] = make_float2(sr, si);
        }
        // Enc rows
        {
            float pr = 1.0f, pi = 0.0f;
            __half* encR = g_Enc + (size_t)(h * 64 + n) * Tn;
            __half* encI = g_Enc + (size_t)(h * 64 + 32 + n) * Tn;
            for (int s = 0; s < Tn; s++) {
                int j = Tn - 1 - s;
                encR[j] = __float2half(pr);
                encI[j] = __float2half(pi);
                float nr = pr * wr - pi * wi, ni = pr * wi + pi * wr;
                pr = nr; pi = ni;
            }
        }
        // Dec columns of M
        {
            float dr = cr * wr - ci * wi, di = cr * wi + ci * wr; // C'*w^1
            for (int i = 0; i < Tn; i++) {
                size_t row = (size_t)(h * Tn + i) * KD;
                g_M[row + 128 + n] = __float2half(2.0f * dr);
                g_M[row + 160 + n] = __float2half(-2.0f * di);
                float nr = dr * wr - di * wi, ni = dr * wi + di * wr;
                dr = nr; di = ni;
            }
        }
        // K[s]
        {
            float kr = cr, ki = ci;
            for (int s = 0; s < Tn; s++) {
                float term = 2.0f * kr;
#pragma unroll
                for (int off = 16; off; off >>= 1)
                    term += __shfl_xor_sync(0xffffffffu, term, off);
                if (n == 0) Ks[s] = term;
                float nr = kr * wr - ki * wi, ni = kr * wi + ki * wr;
                kr = nr; ki = ni;
            }
        }
    }
    __syncthreads();
    // Toeplitz fill
    for (int idx = tid; idx < Tn * Tn; idx += 256) {
        int i = idx >> 7, j = idx & 127;
        float v = (i >= j) ? Ks[i - j] : 0.f;
        g_M[(size_t)(h * Tn + i) * KD + j] = __float2half(v);
    }
}

// =====================================================================
// k_transpose: u (b,l,h) fp32 -> V[h][bc][0..128) fp16
// block: (h-tile 32, c, b); 256 threads
// =====================================================================
__global__ void __launch_bounds__(256)
k_transpose(const float* __restrict__ u) {
    int ht = blockIdx.x, c = blockIdx.y, b = blockIdx.z;
    __shared__ __half ts[32][136];  // [h][j], padded
    int lane = threadIdx.x & 31;    // h within tile
    int r = threadIdx.x >> 5;       // j-subrow

    const float* up = u + ((size_t)b * Ln + (size_t)c * Tn) * Hn + ht * 32;
#pragma unroll
    for (int j0 = 0; j0 < Tn; j0 += 8) {
        int j = j0 + r;
        ts[lane][j] = __float2half(up[(size_t)j * Hn + lane]);
    }
    __syncthreads();

    int row = threadIdx.x >> 3;   // h row 0..31
    int ch = threadIdx.x & 7;     // uint4 chunk
    int bc = b * Cc + c;
    __half* dst = g_V + ((size_t)(ht * 32 + row) * BC + bc) * KD;
    reinterpret_cast<uint4*>(dst)[ch] =
        *reinterpret_cast<const uint4*>(&ts[row][ch * 8]);
    reinterpret_cast<uint4*>(dst)[ch + 8] =
        *reinterpret_cast<const uint4*>(&ts[row][(ch + 8) * 8]);
}

// =====================================================================
// k_encode: per-h GEMM  Xl[64,256] = Enc[64,128] @ V_u[256,128]^T
// + FUSED inter-chunk combine: states -> fp16 into V[..][128..192)
// block per h; 8 warps as 2(m) x 4(n); warp tile 32x64
// =====================================================================
#define LDA1 136
#define LDB1 136
#define LDX  258   // fp32 Xl smem row stride (even -> float2 aligned; 258%32=2 -> 2-way max)
__global__ void __launch_bounds__(256)
k_encode() {
    int h = blockIdx.x;
    int tid = threadIdx.x;
    extern __shared__ __half sm1[];
    __half* As = sm1;                    // [64][LDA1]
    __half* Bs = sm1 + 64 * LDA1;        // [256][LDB1]  (later reused as Xl fp32)

    // load A: 64 rows x 128 halves (16 uint4/row)
    {
        const uint4* src = reinterpret_cast<const uint4*>(g_Enc + (size_t)h * 64 * Tn);
        for (int i = tid; i < 64 * 16; i += 256) {
            int row = i >> 4, ch = i & 15;
            *reinterpret_cast<uint4*>(&As[row * LDA1 + ch * 8]) = src[row * 16 + ch];
        }
    }
    // load B: 256 rows x first 128 halves of V rows (stride KD)
    {
        const __half* vb = g_V + (size_t)h * BC * KD;
        for (int i = tid; i < 256 * 16; i += 256) {
            int row = i >> 4, ch = i & 15;
            *reinterpret_cast<uint4*>(&Bs[row * LDB1 + ch * 8]) =
                *reinterpret_cast<const uint4*>(&vb[(size_t)row * KD + ch * 8]);
        }
    }
    __syncthreads();

    int wid = tid >> 5, lane = tid & 31;
    int wm = wid & 1, wn = wid >> 1;
    int m_base = wm * 32, n_base = wn * 64;

    float acc[2][8][4];
#pragma unroll
    for (int a = 0; a < 2; a++)
#pragma unroll
        for (int bI = 0; bI < 8; bI++)
#pragma unroll
            for (int cI = 0; cI < 4; cI++) acc[a][bI][cI] = 0.f;

    int la = lane & 15;
    int aRowOff = (lane < 16) ? lane : (lane - 16);
    int aColOff = (lane < 16) ? 0 : 8;
    int bRowOff = la & 7;
    int bColOff = (la >> 3) * 8;

#pragma unroll
    for (int kk = 0; kk < 128; kk += 16) {
        unsigned af[2][4];
#pragma unroll
        for (int mf = 0; mf < 2; mf++) {
            int m0 = m_base + mf * 16;
            unsigned addr = smem_u32(&As[(m0 + aRowOff) * LDA1 + kk + aColOff]);
            ldmA(addr, af[mf][0], af[mf][1], af[mf][2], af[mf][3]);
        }
        unsigned bf[8][2];
#pragma unroll
        for (int nf = 0; nf < 8; nf++) {
            int n0 = n_base + nf * 8;
            unsigned addr = smem_u32(&Bs[(n0 + bRowOff) * LDB1 + kk + bColOff]);
            ldmB(addr, bf[nf][0], bf[nf][1]);
        }
#pragma unroll
        for (int mf = 0; mf < 2; mf++)
#pragma unroll
            for (int nf = 0; nf < 8; nf++)
                mma16816(acc[mf][nf], af[mf], bf[nf]);
    }

    // stage Xl[64][BC] in smem (reuse Bs region: 64*258*4 = 66048 <= 69632)
    __syncthreads();
    float* Xls = reinterpret_cast<float*>(Bs);
    {
        int r = lane >> 2, cp = lane & 3;
#pragma unroll
        for (int mf = 0; mf < 2; mf++) {
#pragma unroll
            for (int nf = 0; nf < 8; nf++) {
                int m = m_base + mf * 16 + r;
                int n = n_base + nf * 8 + cp * 2;
                *reinterpret_cast<float2*>(&Xls[m * LDX + n]) =
                    make_float2(acc[mf][nf][0], acc[mf][nf][1]);
                *reinterpret_cast<float2*>(&Xls[(m + 8) * LDX + n]) =
                    make_float2(acc[mf][nf][2], acc[mf][nf][3]);
            }
        }
    }
    __syncthreads();

    // fused combine: thread = (b, n). 32-step sequential chain over chunks.
    {
        int n = tid & 31, b = tid >> 5;
        float2 wT = g_wT[h * Nn + n];
        float XR = 0.f, XI = 0.f;
        __half* vbase = g_V + (size_t)h * BC * KD;
        const float* xR = &Xls[n * LDX];
        const float* xI = &Xls[(n + 32) * LDX];
#pragma unroll 4
        for (int c = 0; c < Cc; c++) {
            int bc = b * Cc + c;
            vbase[(size_t)bc * KD + 128 + n] = __float2half(XR);
            vbase[(size_t)bc * KD + 160 + n] = __float2half(XI);
            float lr = xR[bc], li = xI[bc];
            float nR = wT.x * XR - wT.y * XI + lr;
            float nI = wT.x * XI + wT.y * XR + li;
            XR = nR; XI = nI;
        }
    }
}

// =====================================================================
// k_main: per-h GEMM  Y[128,256] = M[128,192] @ V[256,192]^T
// block per h; 8 warps as 2(m) x 4(n); warp tile 64x64
// =====================================================================
#define LDA2 200
#define LDB2 200
__global__ void __launch_bounds__(256)
k_main() {
    int h = blockIdx.x;
    int tid = threadIdx.x;
    extern __shared__ __half sm2[];
    __half* As = sm2;                     // [128][LDA2]
    __half* Bs = sm2 + 128 * LDA2;        // [256][LDB2]

    // load A: 128 rows x 192 halves (24 uint4/row)
    {
        const uint4* src = reinterpret_cast<const uint4*>(g_M + (size_t)h * Tn * KD);
        for (int i = tid; i < 128 * 24; i += 256) {
            int row = i / 24, ch = i % 24;
            *reinterpret_cast<uint4*>(&As[row * LDA2 + ch * 8]) = src[row * 24 + ch];
        }
    }
    // load B: 256 rows x 192 halves
    {
        const uint4* src = reinterpret_cast<const uint4*>(g_V + (size_t)h * BC * KD);
        for (int i = tid; i < 256 * 24; i += 256) {
            int row = i / 24, ch = i % 24;
            *reinterpret_cast<uint4*>(&Bs[row * LDB2 + ch * 8]) = src[row * 24 + ch];
        }
    }
    __syncthreads();

    int wid = tid >> 5, lane = tid & 31;
    int wm = wid & 1, wn = wid >> 1;
    int m_base = wm * 64, n_base = wn * 64;

    float acc[4][8][4];
#pragma unroll
    for (int a = 0; a < 4; a++)
#pragma unroll
        for (int bI = 0; bI < 8; bI++)
#pragma unroll
            for (int cI = 0; cI < 4; cI++) acc[a][bI][cI] = 0.f;

    int la = lane & 15;
    int aRowOff = (lane < 16) ? lane : (lane - 16);
    int aColOff = (lane < 16) ? 0 : 8;
    int bRowOff = la & 7;
    int bColOff = (la >> 3) * 8;

#pragma unroll
    for (int kk = 0; kk < KD; kk += 16) {
        unsigned af[4][4];
#pragma unroll
        for (int mf = 0; mf < 4; mf++) {
            int m0 = m_base + mf * 16;
            unsigned addr = smem_u32(&As[(m0 + aRowOff) * LDA2 + kk + aColOff]);
            ldmA(addr, af[mf][0], af[mf][1], af[mf][2], af[mf][3]);
        }
        unsigned bf[8][2];
#pragma unroll
        for (int nf = 0; nf < 8; nf++) {
            int n0 = n_base + nf * 8;
            unsigned addr = smem_u32(&Bs[(n0 + bRowOff) * LDB2 + kk + bColOff]);
            ldmB(addr, bf[nf][0], bf[nf][1]);
        }
#pragma unroll
        for (int mf = 0; mf < 4; mf++)
#pragma unroll
            for (int nf = 0; nf < 8; nf++)
                mma16816(acc[mf][nf], af[mf], bf[nf]);
    }

    // store yT[h][bc=n][i=m]
    int r = lane >> 2, cp = lane & 3;
    float* yt = g_yT + (size_t)h * BC * Tn;
#pragma unroll
    for (int mf = 0; mf < 4; mf++) {
#pragma unroll
        for (int nf = 0; nf < 8; nf++) {
            int m = m_base + mf * 16 + r;
            int n = n_base + nf * 8 + cp * 2;
            yt[(size_t)n * Tn + m]           = acc[mf][nf][0];
            yt[(size_t)(n + 1) * Tn + m]     = acc[mf][nf][1];
            yt[(size_t)n * Tn + m + 8]       = acc[mf][nf][2];
            yt[(size_t)(n + 1) * Tn + m + 8] = acc[mf][nf][3];
        }
    }
}

// =====================================================================
// k_final: transpose yT back to (b,l,h), + D*u (skipped when D==0), GELU
// block: (h-tile 32, c, b); 256 threads
// =====================================================================
__global__ void __launch_bounds__(256)
k_final(const float* __restrict__ u, const float* __restrict__ Dp,
        float* __restrict__ out) {
    int ht = blockIdx.x, c = blockIdx.y, b = blockIdx.z;
    __shared__ float ys[128][33];   // [i][h]
    int bc = b * Cc + c;

    {
        int row = threadIdx.x >> 3;   // h 0..31
        int ch = threadIdx.x & 7;
        const float4* src = reinterpret_cast<const float4*>(
            g_yT + ((size_t)(ht * 32 + row) * BC + bc) * Tn);
#pragma unroll
        for (int q = 0; q < 4; q++) {
            int chunk = ch + q * 8;           // 0..31, each 4 floats
            float4 v = src[chunk];
            int i = chunk * 4;
            ys[i + 0][row] = v.x;
            ys[i + 1][row] = v.y;
            ys[i + 2][row] = v.z;
            ys[i + 3][row] = v.w;
        }
    }
    __syncthreads();

    float Dv = *Dp;
    int lane = threadIdx.x & 31;   // h
    int r = threadIdx.x >> 5;
    if (Dv != 0.0f) {
#pragma unroll
        for (int i0 = 0; i0 < Tn; i0 += 8) {
            int i = i0 + r;
            size_t gidx = ((size_t)b * Ln + (size_t)c * Tn + i) * Hn + ht * 32 + lane;
            float v = ys[i][lane] + Dv * u[gidx];
            out[gidx] = gelu_erf(v);
        }
    } else {
#pragma unroll
        for (int i0 = 0; i0 < Tn; i0 += 8) {
            int i = i0 + r;
            size_t gidx = ((size_t)b * Ln + (size_t)c * Tn + i) * Hn + ht * 32 + lane;
            out[gidx] = gelu_erf(ys[i][lane]);
        }
    }
}

// =====================================================================
// launch
// =====================================================================
extern "C" void kernel_launch(void* const* d_in, const int* in_sizes, int n_in,
                              void* d_out, int out_size) {
    (void)in_sizes; (void)n_in; (void)out_size;
    const float* u      = (const float*)d_in[0];
    const float* log_dt = (const float*)d_in[1];
    const float* A_real = (const float*)d_in[2];
    const float* A_imag = (const float*)d_in[3];
    const float* C_real = (const float*)d_in[4];
    const float* C_imag = (const float*)d_in[5];
    const float* D      = (const float*)d_in[6];
    float* out = (float*)d_out;

    static bool attr_done = false;
    if (!attr_done) {
        cudaFuncSetAttribute(k_encode, cudaFuncAttributeMaxDynamicSharedMemorySize,
                             (64 * LDA1 + 256 * LDB1) * 2);
        cudaFuncSetAttribute(k_main, cudaFuncAttributeMaxDynamicSharedMemorySize,
                             (128 * LDA2 + 256 * LDB2) * 2);
        attr_done = true;
    }

    k_tables<<<Hn, 256>>>(log_dt, A_real, A_imag, C_real, C_imag);
    k_transpose<<<dim3(Hn / 32, Cc, Bn), 256>>>(u);
    k_encode<<<Hn, 256, (64 * LDA1 + 256 * LDB1) * 2>>>();
    k_main<<<Hn, 256, (128 * LDA2 + 256 * LDB2) * 2>>>();
    k_final<<<dim3(Hn / 32, Cc, Bn), 256>>>(u, D, out);
}

// round 4
// speedup vs baseline: 1.9711x; 1.0391x over previous
#include <cuda_runtime.h>
#include <cuda_fp16.h>
#include <math.h>

// Problem constants
#define Bn 8
#define Ln 4096
#define Hn 1024
#define Nn 32
#define Tn 128            // chunk length
#define Cc 32             // chunks (Tn*Cc == Ln)
#define BC 256            // B*C columns
#define KD 192            // main GEMM K dim: 128 (u) + 64 (states)

// ---- persistent device buffers (no allocs allowed) ----
__device__ __align__(256) __half  g_Dec[Hn * Tn * 64];        // per-h Dec [128][64] fp16
__device__ __align__(256) float   g_Ks[Hn * Tn];              // per-h kernel taps K[s]
__device__ __align__(256) __half  g_Enc[Hn * 64 * Tn];        // per-h Enc [64][128] fp16
__device__ __align__(256) __half  g_V[(size_t)Hn * BC * KD];  // per-h B op [256][192] (u|states)
__device__ __align__(256) __half  g_yT16[(size_t)Hn * BC * Tn];// per-h output [256][128] fp16
__device__ __align__(256) float2  g_wT[Hn * Nn];              // w^T per (h,n)

// ---- small helpers ----
static __device__ __forceinline__ unsigned smem_u32(const void* p) {
    unsigned r;
    asm("{ .reg .u64 t; cvta.to.shared.u64 t, %1; cvt.u32.u64 %0, t; }"
        : "=r"(r) : "l"(p));
    return r;
}
static __device__ __forceinline__ void ldmA(unsigned addr, unsigned& r0, unsigned& r1,
                                            unsigned& r2, unsigned& r3) {
    asm volatile("ldmatrix.sync.aligned.m8n8.x4.shared.b16 {%0,%1,%2,%3}, [%4];"
                 : "=r"(r0), "=r"(r1), "=r"(r2), "=r"(r3) : "r"(addr));
}
static __device__ __forceinline__ void ldmB(unsigned addr, unsigned& r0, unsigned& r1) {
    asm volatile("ldmatrix.sync.aligned.m8n8.x2.shared.b16 {%0,%1}, [%2];"
                 : "=r"(r0), "=r"(r1) : "r"(addr));
}
static __device__ __forceinline__ void mma16816(float* d, const unsigned* a,
                                                const unsigned* b) {
    asm volatile(
        "mma.sync.aligned.m16n8k16.row.col.f32.f16.f16.f32 "
        "{%0,%1,%2,%3}, {%4,%5,%6,%7}, {%8,%9}, {%0,%1,%2,%3};"
        : "+f"(d[0]), "+f"(d[1]), "+f"(d[2]), "+f"(d[3])
        : "r"(a[0]), "r"(a[1]), "r"(a[2]), "r"(a[3]), "r"(b[0]), "r"(b[1]));
}
static __device__ __forceinline__ float gelu_erf(float v) {
    return 0.5f * v * (1.0f + erff(v * 0.70710678118654752440f));
}

// =====================================================================
// k_tables (fp32, 32 threads per h): coefficient tables
//   w = exp(dt*A), C' = C*(w-1)/A
//   Ks[s] = 2Re(sum_n C'_n w^s)      (Toeplitz built in k_main)
//   Enc[n][j]   = Re(w^{127-j}), Enc[n+32][j] = Im(w^{127-j})
//   Dec[i][n]   = 2Re(C' w^{i+1}), Dec[i][n+32] = -2Im(C' w^{i+1})
//   wT = w^128
// =====================================================================
__global__ void k_tables(const float* __restrict__ log_dt,
                         const float* __restrict__ A_real,
                         const float* __restrict__ A_imag,
                         const float* __restrict__ C_real,
                         const float* __restrict__ C_imag) {
    int h = blockIdx.x;
    int n = threadIdx.x;
    int idx = h * Nn + n;
    float dt = expf(log_dt[h]);
    float Ar = -expf(A_real[idx]);
    float Ai = A_imag[idx];
    float ar = Ar * dt, ai = Ai * dt;
    float er = expf(ar);
    float sn, cs;
    sincosf(ai, &sn, &cs);
    float wr = er * cs, wi = er * sn;

    float den = Ar * Ar + Ai * Ai;
    float e1r = wr - 1.0f, e1i = wi;
    float qr = (e1r * Ar + e1i * Ai) / den;
    float qi = (e1i * Ar - e1r * Ai) / den;
    float Cr = C_real[idx], Ci = C_imag[idx];
    float cr = Cr * qr - Ci * qi;
    float ci = Cr * qi + Ci * qr;

    // wT = w^128 via 7 squarings
    {
        float sr = wr, si = wi;
#pragma unroll
        for (int k = 0; k < 7; k++) {
            float nr = sr * sr - si * si, ni = 2.0f * sr * si;
            sr = nr; si = ni;
        }
        g_wT[h * Nn + n] = make_float2(sr, si);
    }
    // Enc rows
    {
        float pr = 1.0f, pi = 0.0f;
        __half* encR = g_Enc + (size_t)(h * 64 + n) * Tn;
        __half* encI = g_Enc + (size_t)(h * 64 + 32 + n) * Tn;
        for (int s = 0; s < Tn; s++) {
            int j = Tn - 1 - s;
            encR[j] = __float2half(pr);
            encI[j] = __float2half(pi);
            float nr = pr * wr - pi * wi, ni = pr * wi + pi * wr;
            pr = nr; pi = ni;
        }
    }
    // Dec rows
    {
        float dr = cr * wr - ci * wi, di = cr * wi + ci * wr; // C'*w^1
        __half* dec = g_Dec + (size_t)h * Tn * 64;
        for (int i = 0; i < Tn; i++) {
            dec[i * 64 + n]      = __float2half(2.0f * dr);
            dec[i * 64 + 32 + n] = __float2half(-2.0f * di);
            float nr = dr * wr - di * wi, ni = dr * wi + di * wr;
            dr = nr; di = ni;
        }
    }
    // Ks
    {
        float kr = cr, ki = ci;
        float* ks = g_Ks + (size_t)h * Tn;
        for (int s = 0; s < Tn; s++) {
            float term = 2.0f * kr;
#pragma unroll
            for (int off = 16; off; off >>= 1)
                term += __shfl_xor_sync(0xffffffffu, term, off);
            if (n == 0) ks[s] = term;
            float nr = kr * wr - ki * wi, ni = kr * wi + ki * wr;
            kr = nr; ki = ni;
        }
    }
}

// =====================================================================
// k_transpose: u (b,l,h) fp32 -> V[h][bc][0..128) fp16
// block: (h-tile 32, c, b); 256 threads
// =====================================================================
__global__ void __launch_bounds__(256)
k_transpose(const float* __restrict__ u) {
    int ht = blockIdx.x, c = blockIdx.y, b = blockIdx.z;
    __shared__ __half ts[32][136];  // [h][j], padded
    int lane = threadIdx.x & 31;    // h within tile
    int r = threadIdx.x >> 5;       // j-subrow

    const float* up = u + ((size_t)b * Ln + (size_t)c * Tn) * Hn + ht * 32;
#pragma unroll
    for (int j0 = 0; j0 < Tn; j0 += 8) {
        int j = j0 + r;
        ts[lane][j] = __float2half(up[(size_t)j * Hn + lane]);
    }
    __syncthreads();

    int row = threadIdx.x >> 3;   // h row 0..31
    int ch = threadIdx.x & 7;     // uint4 chunk
    int bc = b * Cc + c;
    __half* dst = g_V + ((size_t)(ht * 32 + row) * BC + bc) * KD;
    reinterpret_cast<uint4*>(dst)[ch] =
        *reinterpret_cast<const uint4*>(&ts[row][ch * 8]);
    reinterpret_cast<uint4*>(dst)[ch + 8] =
        *reinterpret_cast<const uint4*>(&ts[row][(ch + 8) * 8]);
}

// =====================================================================
// k_encode: per-h GEMM  Xl[64,256] = Enc[64,128] @ V_u[256,128]^T
// + FUSED inter-chunk combine: states -> fp16 into V[..][128..192)
// block per h; 8 warps as 2(m) x 4(n); warp tile 32x64
// =====================================================================
#define LDA1 136
#define LDB1 136
#define LDX  258   // fp32 Xl smem row stride
__global__ void __launch_bounds__(256)
k_encode() {
    int h = blockIdx.x;
    int tid = threadIdx.x;
    extern __shared__ __half sm1[];
    __half* As = sm1;                    // [64][LDA1]
    __half* Bs = sm1 + 64 * LDA1;        // [256][LDB1]  (later reused as Xl fp32)

    {
        const uint4* src = reinterpret_cast<const uint4*>(g_Enc + (size_t)h * 64 * Tn);
        for (int i = tid; i < 64 * 16; i += 256) {
            int row = i >> 4, ch = i & 15;
            *reinterpret_cast<uint4*>(&As[row * LDA1 + ch * 8]) = src[row * 16 + ch];
        }
    }
    {
        const __half* vb = g_V + (size_t)h * BC * KD;
        for (int i = tid; i < 256 * 16; i += 256) {
            int row = i >> 4, ch = i & 15;
            *reinterpret_cast<uint4*>(&Bs[row * LDB1 + ch * 8]) =
                *reinterpret_cast<const uint4*>(&vb[(size_t)row * KD + ch * 8]);
        }
    }
    __syncthreads();

    int wid = tid >> 5, lane = tid & 31;
    int wm = wid & 1, wn = wid >> 1;
    int m_base = wm * 32, n_base = wn * 64;

    float acc[2][8][4];
#pragma unroll
    for (int a = 0; a < 2; a++)
#pragma unroll
        for (int bI = 0; bI < 8; bI++)
#pragma unroll
            for (int cI = 0; cI < 4; cI++) acc[a][bI][cI] = 0.f;

    int la = lane & 15;
    int aRowOff = (lane < 16) ? lane : (lane - 16);
    int aColOff = (lane < 16) ? 0 : 8;
    int bRowOff = la & 7;
    int bColOff = (la >> 3) * 8;

#pragma unroll
    for (int kk = 0; kk < 128; kk += 16) {
        unsigned af[2][4];
#pragma unroll
        for (int mf = 0; mf < 2; mf++) {
            int m0 = m_base + mf * 16;
            unsigned addr = smem_u32(&As[(m0 + aRowOff) * LDA1 + kk + aColOff]);
            ldmA(addr, af[mf][0], af[mf][1], af[mf][2], af[mf][3]);
        }
        unsigned bf[8][2];
#pragma unroll
        for (int nf = 0; nf < 8; nf++) {
            int n0 = n_base + nf * 8;
            unsigned addr = smem_u32(&Bs[(n0 + bRowOff) * LDB1 + kk + bColOff]);
            ldmB(addr, bf[nf][0], bf[nf][1]);
        }
#pragma unroll
        for (int mf = 0; mf < 2; mf++)
#pragma unroll
            for (int nf = 0; nf < 8; nf++)
                mma16816(acc[mf][nf], af[mf], bf[nf]);
    }

    // stage Xl[64][BC] in smem (reuse Bs region)
    __syncthreads();
    float* Xls = reinterpret_cast<float*>(Bs);
    {
        int r = lane >> 2, cp = lane & 3;
#pragma unroll
        for (int mf = 0; mf < 2; mf++) {
#pragma unroll
            for (int nf = 0; nf < 8; nf++) {
                int m = m_base + mf * 16 + r;
                int n = n_base + nf * 8 + cp * 2;
                *reinterpret_cast<float2*>(&Xls[m * LDX + n]) =
                    make_float2(acc[mf][nf][0], acc[mf][nf][1]);
                *reinterpret_cast<float2*>(&Xls[(m + 8) * LDX + n]) =
                    make_float2(acc[mf][nf][2], acc[mf][nf][3]);
            }
        }
    }
    __syncthreads();

    // fused combine: thread = (b, n). 32-step sequential chain over chunks.
    {
        int n = tid & 31, b = tid >> 5;
        float2 wT = g_wT[h * Nn + n];
        float XR = 0.f, XI = 0.f;
        __half* vbase = g_V + (size_t)h * BC * KD;
        const float* xR = &Xls[n * LDX];
        const float* xI = &Xls[(n + 32) * LDX];
#pragma unroll 4
        for (int c = 0; c < Cc; c++) {
            int bc = b * Cc + c;
            vbase[(size_t)bc * KD + 128 + n] = __float2half(XR);
            vbase[(size_t)bc * KD + 160 + n] = __float2half(XI);
            float lr = xR[bc], li = xI[bc];
            float nR = wT.x * XR - wT.y * XI + lr;
            float nI = wT.x * XI + wT.y * XR + li;
            XR = nR; XI = nI;
        }
    }
}

// =====================================================================
// k_main: per-(h, s) GEMM  Y[128, 128] = M[128,192] @ V[s*128..][192]^T
// A panel built in-kernel: Toeplitz(Ks) | Dec. Output staged -> fp16.
// block 256 = 8 warps as 2(m) x 4(n); warp tile 64x32; 2 CTAs/SM.
// =====================================================================
#define LDA2 200
#define LDB2 200
#define LDO  136
__global__ void __launch_bounds__(256, 2)
k_main() {
    int h = blockIdx.x;
    int s = blockIdx.y;          // bc-half
    int tid = threadIdx.x;
    extern __shared__ __half sm2[];
    __half* As = sm2;                     // [128][LDA2]
    __half* Bs = sm2 + 128 * LDA2;        // [128][LDB2]
    __shared__ float Ksh[Tn];

    // load Ks into smem
    if (tid < Tn) Ksh[tid] = g_Ks[(size_t)h * Tn + tid];
    // load Dec into As cols [128..192)
    {
        const uint4* src = reinterpret_cast<const uint4*>(g_Dec + (size_t)h * Tn * 64);
        for (int i = tid; i < 128 * 8; i += 256) {
            int row = i >> 3, ch = i & 7;
            *reinterpret_cast<uint4*>(&As[row * LDA2 + 128 + ch * 8]) = src[row * 8 + ch];
        }
    }
    // load B: 128 rows x 192 halves
    {
        const uint4* src = reinterpret_cast<const uint4*>(
            g_V + ((size_t)h * BC + s * 128) * KD);
        for (int i = tid; i < 128 * 24; i += 256) {
            int row = i / 24, ch = i % 24;
            *reinterpret_cast<uint4*>(&Bs[row * LDB2 + ch * 8]) = src[row * 24 + ch];
        }
    }
    __syncthreads();
    // Toeplitz fill from Ksh (cols 0..127)
    for (int idx = tid; idx < 128 * 128; idx += 256) {
        int i = idx >> 7, j = idx & 127;
        As[i * LDA2 + j] = __float2half((i >= j) ? Ksh[i - j] : 0.f);
    }
    __syncthreads();

    int wid = tid >> 5, lane = tid & 31;
    int wm = wid & 1, wn = wid >> 1;
    int m_base = wm * 64, n_base = wn * 32;

    float acc[4][4][4];
#pragma unroll
    for (int a = 0; a < 4; a++)
#pragma unroll
        for (int bI = 0; bI < 4; bI++)
#pragma unroll
            for (int cI = 0; cI < 4; cI++) acc[a][bI][cI] = 0.f;

    int la = lane & 15;
    int aRowOff = (lane < 16) ? lane : (lane - 16);
    int aColOff = (lane < 16) ? 0 : 8;
    int bRowOff = la & 7;
    int bColOff = (la >> 3) * 8;

#pragma unroll
    for (int kk = 0; kk < KD; kk += 16) {
        unsigned af[4][4];
#pragma unroll
        for (int mf = 0; mf < 4; mf++) {
            int m0 = m_base + mf * 16;
            unsigned addr = smem_u32(&As[(m0 + aRowOff) * LDA2 + kk + aColOff]);
            ldmA(addr, af[mf][0], af[mf][1], af[mf][2], af[mf][3]);
        }
        unsigned bf[4][2];
#pragma unroll
        for (int nf = 0; nf < 4; nf++) {
            int n0 = n_base + nf * 8;
            unsigned addr = smem_u32(&Bs[(n0 + bRowOff) * LDB2 + kk + bColOff]);
            ldmB(addr, bf[nf][0], bf[nf][1]);
        }
#pragma unroll
        for (int mf = 0; mf < 4; mf++)
#pragma unroll
            for (int nf = 0; nf < 4; nf++)
                mma16816(acc[mf][nf], af[mf], bf[nf]);
    }

    // stage output [128 bc][128 m] fp16 in smem (reuse As region), coalesced store
    __syncthreads();
    __half* ot = As;   // 128*LDO*2 = 34.8KB <= As region 51.2KB
    {
        int r = lane >> 2, cp = lane & 3;
#pragma unroll
        for (int mf = 0; mf < 4; mf++) {
            int m = m_base + mf * 16 + r;
#pragma unroll
            for (int nf = 0; nf < 4; nf++) {
                int n = n_base + nf * 8 + cp * 2;
                ot[n * LDO + m]           = __float2half(acc[mf][nf][0]);
                ot[(n + 1) * LDO + m]     = __float2half(acc[mf][nf][1]);
                ot[n * LDO + m + 8]       = __float2half(acc[mf][nf][2]);
                ot[(n + 1) * LDO + m + 8] = __float2half(acc[mf][nf][3]);
            }
        }
    }
    __syncthreads();
    {
        __half* dst = g_yT16 + ((size_t)h * BC + s * 128) * Tn;
        for (int i = tid; i < 128 * 16; i += 256) {
            int row = i >> 4, ch = i & 15;
            *reinterpret_cast<uint4*>(&dst[row * Tn + ch * 8]) =
                *reinterpret_cast<const uint4*>(&ot[row * LDO + ch * 8]);
        }
    }
}

// =====================================================================
// k_final: transpose yT16 back to (b,l,h), + D*u (skipped when D==0), GELU
// block: (h-tile 32, c, b); 256 threads
// =====================================================================
__global__ void __launch_bounds__(256)
k_final(const float* __restrict__ u, const float* __restrict__ Dp,
        float* __restrict__ out) {
    int ht = blockIdx.x, c = blockIdx.y, b = blockIdx.z;
    __shared__ float ys[128][33];   // [i][h]
    int bc = b * Cc + c;

    {
#pragma unroll
        for (int q = 0; q < 2; q++) {
            int idx = threadIdx.x + q * 256;       // 0..511
            int row = idx >> 4;                    // h in tile 0..31
            int ch = idx & 15;                     // uint4 chunk
            const uint4* src = reinterpret_cast<const uint4*>(
                g_yT16 + ((size_t)(ht * 32 + row) * BC + bc) * Tn);
            uint4 v = src[ch];
            const __half* hp = reinterpret_cast<const __half*>(&v);
            int i = ch * 8;
#pragma unroll
            for (int k = 0; k < 8; k++)
                ys[i + k][row] = __half2float(hp[k]);
        }
    }
    __syncthreads();

    float Dv = *Dp;
    int lane = threadIdx.x & 31;   // h
    int r = threadIdx.x >> 5;
    if (Dv != 0.0f) {
#pragma unroll
        for (int i0 = 0; i0 < Tn; i0 += 8) {
            int i = i0 + r;
            size_t gidx = ((size_t)b * Ln + (size_t)c * Tn + i) * Hn + ht * 32 + lane;
            float v = ys[i][lane] + Dv * u[gidx];
            out[gidx] = gelu_erf(v);
        }
    } else {
#pragma unroll
        for (int i0 = 0; i0 < Tn; i0 += 8) {
            int i = i0 + r;
            size_t gidx = ((size_t)b * Ln + (size_t)c * Tn + i) * Hn + ht * 32 + lane;
            out[gidx] = gelu_erf(ys[i][lane]);
        }
    }
}

// =====================================================================
// launch
// =====================================================================
extern "C" void kernel_launch(void* const* d_in, const int* in_sizes, int n_in,
                              void* d_out, int out_size) {
    (void)in_sizes; (void)n_in; (void)out_size;
    const float* u      = (const float*)d_in[0];
    const float* log_dt = (const float*)d_in[1];
    const float* A_real = (const float*)d_in[2];
    const float* A_imag = (const float*)d_in[3];
    const float* C_real = (const float*)d_in[4];
    const float* C_imag = (const float*)d_in[5];
    const float* D      = (const float*)d_in[6];
    float* out = (float*)d_out;

    static bool attr_done = false;
    if (!attr_done) {
        cudaFuncSetAttribute(k_encode, cudaFuncAttributeMaxDynamicSharedMemorySize,
                             (64 * LDA1 + 256 * LDB1) * 2);
        cudaFuncSetAttribute(k_main, cudaFuncAttributeMaxDynamicSharedMemorySize,
                             (128 * LDA2 + 128 * LDB2) * 2);
        attr_done = true;
    }

    k_tables<<<Hn, 32>>>(log_dt, A_real, A_imag, C_real, C_imag);
    k_transpose<<<dim3(Hn / 32, Cc, Bn), 256>>>(u);
    k_encode<<<Hn, 256, (64 * LDA1 + 256 * LDB1) * 2>>>();
    k_main<<<dim3(Hn, 2), 256, (128 * LDA2 + 128 * LDB2) * 2>>>();
    k_final<<<dim3(Hn / 32, Cc, Bn), 256>>>(u, D, out);
}

// round 5
// speedup vs baseline: 2.2325x; 1.1326x over previous
#include <cuda_runtime.h>
#include <cuda_fp16.h>
#include <math.h>

// Problem constants
#define Bn 8
#define Ln 4096
#define Hn 1024
#define Nn 32
#define Tn 128            // chunk length
#define Cc 32             // chunks (Tn*Cc == Ln)
#define BC 256            // B*C columns
#define KD 192            // main GEMM K dim: 128 (u) + 64 (states)

// ---- persistent device buffers (no allocs allowed) ----
__device__ __align__(256) __half  g_Dec[Hn * Tn * 64];         // per-h Dec [128][64] fp16
__device__ __align__(256) float   g_Ks[Hn * Tn];               // per-h kernel taps K[s]
__device__ __align__(256) __half  g_Enc[Hn * 64 * Tn];         // per-h Enc [64][128] fp16
__device__ __align__(256) __half  g_V[(size_t)Hn * BC * KD];   // per-h B op [256][192]
__device__ __align__(256) __half  g_yT16[(size_t)Hn * BC * Tn];// per-h output [256][128] fp16
__device__ __align__(256) float2  g_wT[Hn * Nn];               // w^T per (h,n)

// ---- small helpers ----
static __device__ __forceinline__ unsigned smem_u32(const void* p) {
    unsigned r;
    asm("{ .reg .u64 t; cvta.to.shared.u64 t, %1; cvt.u32.u64 %0, t; }"
        : "=r"(r) : "l"(p));
    return r;
}
static __device__ __forceinline__ void ldmA(unsigned addr, unsigned& r0, unsigned& r1,
                                            unsigned& r2, unsigned& r3) {
    asm volatile("ldmatrix.sync.aligned.m8n8.x4.shared.b16 {%0,%1,%2,%3}, [%4];"
                 : "=r"(r0), "=r"(r1), "=r"(r2), "=r"(r3) : "r"(addr));
}
static __device__ __forceinline__ void ldmB(unsigned addr, unsigned& r0, unsigned& r1) {
    asm volatile("ldmatrix.sync.aligned.m8n8.x2.shared.b16 {%0,%1}, [%2];"
                 : "=r"(r0), "=r"(r1) : "r"(addr));
}
static __device__ __forceinline__ void mma16816(float* d, const unsigned* a,
                                                const unsigned* b) {
    asm volatile(
        "mma.sync.aligned.m16n8k16.row.col.f32.f16.f16.f32 "
        "{%0,%1,%2,%3}, {%4,%5,%6,%7}, {%8,%9}, {%0,%1,%2,%3};"
        : "+f"(d[0]), "+f"(d[1]), "+f"(d[2]), "+f"(d[3])
        : "r"(a[0]), "r"(a[1]), "r"(a[2]), "r"(a[3]), "r"(b[0]), "r"(b[1]));
}
static __device__ __forceinline__ float gelu_erf(float v) {
    return 0.5f * v * (1.0f + erff(v * 0.70710678118654752440f));
}

// =====================================================================
// k_tables (parallel, 256 threads per h): direct per-(s,n) evaluation
//   w^s = exp(s*ar) * cis(s*ai)   (2-ulp sinf/cosf; no chain accumulation)
//   Ks[s] = 2 Re(sum_n C'_n w^s)
//   Enc[n][127-s]=Re(w^s), Enc[n+32][127-s]=Im(w^s)  (smem-staged, coalesced out)
//   Dec[s][n]=2Re(C' w^{s+1}), Dec[s][32+n]=-2Im(C' w^{s+1})  (coalesced)
//   wT = w^128
// =====================================================================
#define LDE 136
__global__ void __launch_bounds__(256)
k_tables(const float* __restrict__ log_dt,
         const float* __restrict__ A_real,
         const float* __restrict__ A_imag,
         const float* __restrict__ C_real,
         const float* __restrict__ C_imag) {
    int h = blockIdx.x;
    int tid = threadIdx.x;
    __shared__ float s_ar[32], s_ai[32], s_cr[32], s_ci[32];
    __shared__ __half encS[64 * LDE];

    if (tid < 32) {
        int n = tid, idx = h * Nn + n;
        float dt = expf(log_dt[h]);
        float Ar = -expf(A_real[idx]);
        float Ai = A_imag[idx];
        float ar = Ar * dt, ai = Ai * dt;
        float er = expf(ar);
        float sn, cs;
        sincosf(ai, &sn, &cs);
        float wr = er * cs, wi = er * sn;
        float den = Ar * Ar + Ai * Ai;
        float e1r = wr - 1.0f, e1i = wi;
        float qr = (e1r * Ar + e1i * Ai) / den;
        float qi = (e1i * Ar - e1r * Ai) / den;
        float Cr = C_real[idx], Ci = C_imag[idx];
        s_ar[n] = ar; s_ai[n] = ai;
        s_cr[n] = Cr * qr - Ci * qi;
        s_ci[n] = Cr * qi + Ci * qr;
        // wT = w^128 direct
        float erT = expf(128.f * ar);
        float snT, csT;
        sincosf(128.f * ai, &snT, &csT);
        g_wT[h * Nn + n] = make_float2(erT * csT, erT * snT);
    }
    __syncthreads();

    int n = tid & 31, w = tid >> 5;     // lane = mode, warp covers 16 s values
#pragma unroll
    for (int q = 0; q < 16; q++) {
        int s = w * 16 + q;
        float ar = s_ar[n], ai = s_ai[n];
        float fs = (float)s;
        float er = expf(fs * ar);
        float sn, cs;
        sincosf(fs * ai, &sn, &cs);
        float wr = er * cs, wi = er * sn;          // w^s
        encS[n * LDE + (127 - s)]        = __float2half(wr);
        encS[(n + 32) * LDE + (127 - s)] = __float2half(wi);

        float er1 = expf((fs + 1.f) * ar);
        float sn1, cs1;
        sincosf((fs + 1.f) * ai, &sn1, &cs1);
        float pr = er1 * cs1, pi = er1 * sn1;      // w^{s+1}
        float cr = s_cr[n], ci = s_ci[n];
        float dr = cr * pr - ci * pi, di = cr * pi + ci * pr;
        __half* dec = g_Dec + (size_t)h * Tn * 64 + s * 64;
        dec[n]      = __float2half(2.0f * dr);
        dec[32 + n] = __float2half(-2.0f * di);

        float term = 2.0f * (cr * wr - ci * wi);
#pragma unroll
        for (int off = 16; off; off >>= 1)
            term += __shfl_xor_sync(0xffffffffu, term, off);
        if (n == 0) g_Ks[(size_t)h * Tn + s] = term;
    }
    __syncthreads();

    // coalesced Enc writeout: 64 rows x 16 uint4
    {
        uint4* dst = reinterpret_cast<uint4*>(g_Enc + (size_t)h * 64 * Tn);
        for (int i = tid; i < 64 * 16; i += 256) {
            int row = i >> 4, ch = i & 15;
            dst[i] = *reinterpret_cast<const uint4*>(&encS[row * LDE + ch * 8]);
        }
    }
}

// =====================================================================
// k_transpose: u (b,l,h) fp32 -> V[h][bc][0..128) fp16
// =====================================================================
__global__ void __launch_bounds__(256)
k_transpose(const float* __restrict__ u) {
    int ht = blockIdx.x, c = blockIdx.y, b = blockIdx.z;
    __shared__ __half ts[32][136];
    int lane = threadIdx.x & 31;
    int r = threadIdx.x >> 5;

    const float* up = u + ((size_t)b * Ln + (size_t)c * Tn) * Hn + ht * 32;
#pragma unroll
    for (int j0 = 0; j0 < Tn; j0 += 8) {
        int j = j0 + r;
        ts[lane][j] = __float2half(up[(size_t)j * Hn + lane]);
    }
    __syncthreads();

    int row = threadIdx.x >> 3;
    int ch = threadIdx.x & 7;
    int bc = b * Cc + c;
    __half* dst = g_V + ((size_t)(ht * 32 + row) * BC + bc) * KD;
    reinterpret_cast<uint4*>(dst)[ch] =
        *reinterpret_cast<const uint4*>(&ts[row][ch * 8]);
    reinterpret_cast<uint4*>(dst)[ch + 8] =
        *reinterpret_cast<const uint4*>(&ts[row][(ch + 8) * 8]);
}

// =====================================================================
// k_encode: per-h GEMM  Xl[64,256] = Enc[64,128] @ V_u[256,128]^T
// + fused inter-chunk combine -> fp16 states into V[..][128..192)
// =====================================================================
#define LDA1 136
#define LDB1 136
#define LDX  258
__global__ void __launch_bounds__(256)
k_encode() {
    int h = blockIdx.x;
    int tid = threadIdx.x;
    extern __shared__ __half sm1[];
    __half* As = sm1;                    // [64][LDA1]
    __half* Bs = sm1 + 64 * LDA1;        // [256][LDB1]  (reused as Xl fp32)

    {
        const uint4* src = reinterpret_cast<const uint4*>(g_Enc + (size_t)h * 64 * Tn);
        for (int i = tid; i < 64 * 16; i += 256) {
            int row = i >> 4, ch = i & 15;
            *reinterpret_cast<uint4*>(&As[row * LDA1 + ch * 8]) = src[row * 16 + ch];
        }
    }
    {
        const __half* vb = g_V + (size_t)h * BC * KD;
        for (int i = tid; i < 256 * 16; i += 256) {
            int row = i >> 4, ch = i & 15;
            *reinterpret_cast<uint4*>(&Bs[row * LDB1 + ch * 8]) =
                *reinterpret_cast<const uint4*>(&vb[(size_t)row * KD + ch * 8]);
        }
    }
    __syncthreads();

    int wid = tid >> 5, lane = tid & 31;
    int wm = wid & 1, wn = wid >> 1;
    int m_base = wm * 32, n_base = wn * 64;

    float acc[2][8][4];
#pragma unroll
    for (int a = 0; a < 2; a++)
#pragma unroll
        for (int bI = 0; bI < 8; bI++)
#pragma unroll
            for (int cI = 0; cI < 4; cI++) acc[a][bI][cI] = 0.f;

    int la = lane & 15;
    int aRowOff = (lane < 16) ? lane : (lane - 16);
    int aColOff = (lane < 16) ? 0 : 8;
    int bRowOff = la & 7;
    int bColOff = (la >> 3) * 8;

#pragma unroll
    for (int kk = 0; kk < 128; kk += 16) {
        unsigned af[2][4];
#pragma unroll
        for (int mf = 0; mf < 2; mf++) {
            int m0 = m_base + mf * 16;
            unsigned addr = smem_u32(&As[(m0 + aRowOff) * LDA1 + kk + aColOff]);
            ldmA(addr, af[mf][0], af[mf][1], af[mf][2], af[mf][3]);
        }
        unsigned bf[8][2];
#pragma unroll
        for (int nf = 0; nf < 8; nf++) {
            int n0 = n_base + nf * 8;
            unsigned addr = smem_u32(&Bs[(n0 + bRowOff) * LDB1 + kk + bColOff]);
            ldmB(addr, bf[nf][0], bf[nf][1]);
        }
#pragma unroll
        for (int mf = 0; mf < 2; mf++)
#pragma unroll
            for (int nf = 0; nf < 8; nf++)
                mma16816(acc[mf][nf], af[mf], bf[nf]);
    }

    __syncthreads();
    float* Xls = reinterpret_cast<float*>(Bs);
    {
        int r = lane >> 2, cp = lane & 3;
#pragma unroll
        for (int mf = 0; mf < 2; mf++) {
#pragma unroll
            for (int nf = 0; nf < 8; nf++) {
                int m = m_base + mf * 16 + r;
                int n = n_base + nf * 8 + cp * 2;
                *reinterpret_cast<float2*>(&Xls[m * LDX + n]) =
                    make_float2(acc[mf][nf][0], acc[mf][nf][1]);
                *reinterpret_cast<float2*>(&Xls[(m + 8) * LDX + n]) =
                    make_float2(acc[mf][nf][2], acc[mf][nf][3]);
            }
        }
    }
    __syncthreads();

    {
        int n = tid & 31, b = tid >> 5;
        float2 wT = g_wT[h * Nn + n];
        float XR = 0.f, XI = 0.f;
        __half* vbase = g_V + (size_t)h * BC * KD;
        const float* xR = &Xls[n * LDX];
        const float* xI = &Xls[(n + 32) * LDX];
#pragma unroll 4
        for (int c = 0; c < Cc; c++) {
            int bc = b * Cc + c;
            vbase[(size_t)bc * KD + 128 + n] = __float2half(XR);
            vbase[(size_t)bc * KD + 160 + n] = __float2half(XI);
            float lr = xR[bc], li = xI[bc];
            float nR = wT.x * XR - wT.y * XI + lr;
            float nI = wT.x * XI + wT.y * XR + li;
            XR = nR; XI = nI;
        }
    }
}

// =====================================================================
// k_main: per-(h, s) GEMM  Y[128,128] = [Toep(Ks)|Dec] @ V_tile^T
// Register double-buffered pipeline; triangular k-step skip for m<64
// warps (wm = wid>>2 -> one short + one long warp per SMSP).
// =====================================================================
#define LDA2 200
#define LDB2 200
#define LDO  136
__global__ void __launch_bounds__(256, 2)
k_main() {
    int h = blockIdx.x;
    int s = blockIdx.y;
    int tid = threadIdx.x;
    extern __shared__ __half sm2[];
    __half* As = sm2;                     // [128][LDA2]
    __half* Bs = sm2 + 128 * LDA2;        // [128][LDB2]
    __shared__ float Ksh[Tn];

    if (tid < Tn) Ksh[tid] = g_Ks[(size_t)h * Tn + tid];
    // Dec -> As cols [128..192)
    {
        const uint4* src = reinterpret_cast<const uint4*>(g_Dec + (size_t)h * Tn * 64);
        for (int i = tid; i < 128 * 8; i += 256) {
            int row = i >> 3, ch = i & 7;
            *reinterpret_cast<uint4*>(&As[row * LDA2 + 128 + ch * 8]) = src[row * 8 + ch];
        }
    }
    // B tile: 128 rows x 192 halves
    {
        const uint4* src = reinterpret_cast<const uint4*>(
            g_V + ((size_t)h * BC + s * 128) * KD);
        for (int i = tid; i < 128 * 24; i += 256) {
            int row = i / 24, ch = i % 24;
            *reinterpret_cast<uint4*>(&Bs[row * LDB2 + ch * 8]) = src[row * 24 + ch];
        }
    }
    __syncthreads();
    // vectorized Toeplitz fill (cols 0..127) from Ksh
    for (int i = tid; i < 128 * 16; i += 256) {
        int row = i >> 4, ch = i & 15;
        int j0 = ch * 8;
        __half hv[8];
#pragma unroll
        for (int k = 0; k < 8; k++) {
            int j = j0 + k;
            hv[k] = __float2half((row >= j) ? Ksh[row - j] : 0.f);
        }
        *reinterpret_cast<uint4*>(&As[row * LDA2 + j0]) =
            *reinterpret_cast<const uint4*>(hv);
    }
    __syncthreads();

    int wid = tid >> 5, lane = tid & 31;
    int wm = wid >> 2, wn = wid & 3;     // balanced: each SMSP gets wm0+wm1
    int m_base = wm * 64, n_base = wn * 32;

    float acc[4][4][4];
#pragma unroll
    for (int a = 0; a < 4; a++)
#pragma unroll
        for (int bI = 0; bI < 4; bI++)
#pragma unroll
            for (int cI = 0; cI < 4; cI++) acc[a][bI][cI] = 0.f;

    int la = lane & 15;
    int aRowOff = (lane < 16) ? lane : (lane - 16);
    int aColOff = (lane < 16) ? 0 : 8;
    int bRowOff = la & 7;
    int bColOff = (la >> 3) * 8;

    unsigned aBase = smem_u32(&As[(m_base + aRowOff) * LDA2 + aColOff]);
    unsigned bBase = smem_u32(&Bs[(n_base + bRowOff) * LDB2 + bColOff]);

    unsigned af[2][4][4];
    unsigned bf[2][4][2];

#define LOAD_AB(buf, ks_)                                                     \
    {                                                                         \
        const int kk_ = (ks_) * 16;                                           \
        _Pragma("unroll")                                                     \
        for (int mf = 0; mf < 4; mf++)                                        \
            ldmA(aBase + (unsigned)((mf * 16 * LDA2 + kk_) * 2),              \
                 af[buf][mf][0], af[buf][mf][1], af[buf][mf][2], af[buf][mf][3]); \
        _Pragma("unroll")                                                     \
        for (int nf = 0; nf < 4; nf++)                                        \
            ldmB(bBase + (unsigned)((nf * 8 * LDB2 + kk_) * 2),               \
                 bf[buf][nf][0], bf[buf][nf][1]);                             \
    }
#define MMA_STEP(buf)                                                         \
    {                                                                         \
        _Pragma("unroll")                                                     \
        for (int mf = 0; mf < 4; mf++)                                        \
            _Pragma("unroll")                                                 \
            for (int nf = 0; nf < 4; nf++)                                    \
                mma16816(acc[mf][nf], af[buf][mf], bf[buf][nf]);              \
    }

    if (wm == 0) {
        // Toeplitz block all-zero for j>=64 when i<64: k-steps {0,1,2,3,8,9,10,11}
        LOAD_AB(0, 0)
#pragma unroll
        for (int it = 0; it < 8; it++) {
            int cur = it & 1;
            if (it < 7) {
                int nks = (it + 1 < 4) ? (it + 1) : (it + 5);
                LOAD_AB(cur ^ 1, nks)
            }
            MMA_STEP(cur)
        }
    } else {
        LOAD_AB(0, 0)
#pragma unroll
        for (int it = 0; it < 12; it++) {
            int cur = it & 1;
            if (it < 11) LOAD_AB(cur ^ 1, it + 1)
            MMA_STEP(cur)
        }
    }
#undef LOAD_AB
#undef MMA_STEP

    // stage output [128 bc][128 m] fp16 in smem (reuse As), coalesced store
    __syncthreads();
    __half* ot = As;
    {
        int r = lane >> 2, cp = lane & 3;
#pragma unroll
        for (int mf = 0; mf < 4; mf++) {
            int m = m_base + mf * 16 + r;
#pragma unroll
            for (int nf = 0; nf < 4; nf++) {
                int n = n_base + nf * 8 + cp * 2;
                ot[n * LDO + m]           = __float2half(acc[mf][nf][0]);
                ot[(n + 1) * LDO + m]     = __float2half(acc[mf][nf][1]);
                ot[n * LDO + m + 8]       = __float2half(acc[mf][nf][2]);
                ot[(n + 1) * LDO + m + 8] = __float2half(acc[mf][nf][3]);
            }
        }
    }
    __syncthreads();
    {
        __half* dst = g_yT16 + ((size_t)h * BC + s * 128) * Tn;
        for (int i = tid; i < 128 * 16; i += 256) {
            int row = i >> 4, ch = i & 15;
            *reinterpret_cast<uint4*>(&dst[row * Tn + ch * 8]) =
                *reinterpret_cast<const uint4*>(&ot[row * LDO + ch * 8]);
        }
    }
}

// =====================================================================
// k_final: transpose yT16 -> (b,l,h), + D*u (skipped when D==0), GELU
// =====================================================================
__global__ void __launch_bounds__(256)
k_final(const float* __restrict__ u, const float* __restrict__ Dp,
        float* __restrict__ out) {
    int ht = blockIdx.x, c = blockIdx.y, b = blockIdx.z;
    __shared__ float ys[128][33];
    int bc = b * Cc + c;

    {
#pragma unroll
        for (int q = 0; q < 2; q++) {
            int idx = threadIdx.x + q * 256;
            int row = idx >> 4;
            int ch = idx & 15;
            const uint4* src = reinterpret_cast<const uint4*>(
                g_yT16 + ((size_t)(ht * 32 + row) * BC + bc) * Tn);
            uint4 v = src[ch];
            const __half* hp = reinterpret_cast<const __half*>(&v);
            int i = ch * 8;
#pragma unroll
            for (int k = 0; k < 8; k++)
                ys[i + k][row] = __half2float(hp[k]);
        }
    }
    __syncthreads();

    float Dv = *Dp;
    int lane = threadIdx.x & 31;
    int r = threadIdx.x >> 5;
    if (Dv != 0.0f) {
#pragma unroll
        for (int i0 = 0; i0 < Tn; i0 += 8) {
            int i = i0 + r;
            size_t gidx = ((size_t)b * Ln + (size_t)c * Tn + i) * Hn + ht * 32 + lane;
            float v = ys[i][lane] + Dv * u[gidx];
            out[gidx] = gelu_erf(v);
        }
    } else {
#pragma unroll
        for (int i0 = 0; i0 < Tn; i0 += 8) {
            int i = i0 + r;
            size_t gidx = ((size_t)b * Ln + (size_t)c * Tn + i) * Hn + ht * 32 + lane;
            out[gidx] = gelu_erf(ys[i][lane]);
        }
    }
}

// =====================================================================
// launch
// =====================================================================
extern "C" void kernel_launch(void* const* d_in, const int* in_sizes, int n_in,
                              void* d_out, int out_size) {
    (void)in_sizes; (void)n_in; (void)out_size;
    const float* u      = (const float*)d_in[0];
    const float* log_dt = (const float*)d_in[1];
    const float* A_real = (const float*)d_in[2];
    const float* A_imag = (const float*)d_in[3];
    const float* C_real = (const float*)d_in[4];
    const float* C_imag = (const float*)d_in[5];
    const float* D      = (const float*)d_in[6];
    float* out = (float*)d_out;

    static bool attr_done = false;
    if (!attr_done) {
        cudaFuncSetAttribute(k_encode, cudaFuncAttributeMaxDynamicSharedMemorySize,
                             (64 * LDA1 + 256 * LDB1) * 2);
        cudaFuncSetAttribute(k_main, cudaFuncAttributeMaxDynamicSharedMemorySize,
                             (128 * LDA2 + 128 * LDB2) * 2);
        attr_done = true;
    }

    k_tables<<<Hn, 256>>>(log_dt, A_real, A_imag, C_real, C_imag);
    k_transpose<<<dim3(Hn / 32, Cc, Bn), 256>>>(u);
    k_encode<<<Hn, 256, (64 * LDA1 + 256 * LDB1) * 2>>>();
    k_main<<<dim3(Hn, 2), 256, (128 * LDA2 + 128 * LDB2) * 2>>>();
    k_final<<<dim3(Hn / 32, Cc, Bn), 256>>>(u, D, out);
}

// round 6
// speedup vs baseline: 2.7417x; 1.2281x over previous
#include <cuda_runtime.h>
#include <cuda_fp16.h>
#include <math.h>

// Problem constants
#define Bn 8
#define Ln 4096
#define Hn 1024
#define Nn 32
#define Tn 128            // chunk length
#define Cc 32             // chunks (Tn*Cc == Ln)
#define BC 256            // B*C columns
#define KD 192            // main GEMM K dim: 128 (u) + 64 (states)

// ---- persistent device buffers (no allocs allowed) ----
__device__ __align__(256) __half  g_V[(size_t)Hn * BC * KD];   // per-h B op [256][192]
__device__ __align__(256) __half  g_yT16[(size_t)Hn * BC * Tn];// per-h output [256][128] fp16

// ---- small helpers ----
static __device__ __forceinline__ unsigned smem_u32(const void* p) {
    unsigned r;
    asm("{ .reg .u64 t; cvta.to.shared.u64 t, %1; cvt.u32.u64 %0, t; }"
        : "=r"(r) : "l"(p));
    return r;
}
static __device__ __forceinline__ void cp16(unsigned dst, const void* src) {
    asm volatile("cp.async.cg.shared.global [%0], [%1], 16;" :: "r"(dst), "l"(src));
}
static __device__ __forceinline__ void cp_commit() {
    asm volatile("cp.async.commit_group;");
}
static __device__ __forceinline__ void cp_wait_all() {
    asm volatile("cp.async.wait_group 0;");
}
static __device__ __forceinline__ void ldmA(unsigned addr, unsigned& r0, unsigned& r1,
                                            unsigned& r2, unsigned& r3) {
    asm volatile("ldmatrix.sync.aligned.m8n8.x4.shared.b16 {%0,%1,%2,%3}, [%4];"
                 : "=r"(r0), "=r"(r1), "=r"(r2), "=r"(r3) : "r"(addr));
}
static __device__ __forceinline__ void ldmB(unsigned addr, unsigned& r0, unsigned& r1) {
    asm volatile("ldmatrix.sync.aligned.m8n8.x2.shared.b16 {%0,%1}, [%2];"
                 : "=r"(r0), "=r"(r1) : "r"(addr));
}
static __device__ __forceinline__ void mma16816(float* d, const unsigned* a,
                                                const unsigned* b) {
    asm volatile(
        "mma.sync.aligned.m16n8k16.row.col.f32.f16.f16.f32 "
        "{%0,%1,%2,%3}, {%4,%5,%6,%7}, {%8,%9}, {%0,%1,%2,%3};"
        : "+f"(d[0]), "+f"(d[1]), "+f"(d[2]), "+f"(d[3])
        : "r"(a[0]), "r"(a[1]), "r"(a[2]), "r"(a[3]), "r"(b[0]), "r"(b[1]));
}
static __device__ __forceinline__ float gelu_erf(float v) {
    return 0.5f * v * (1.0f + erff(v * 0.70710678118654752440f));
}

// Per-mode recurrence params: w = exp(dt*A), c' = C*(w-1)/A
// Computed by 32 threads into smem arrays.
struct ModeParams {
    float ar[32], ai[32];       // log|w|, arg w
    float wr[32], wi[32];       // w
    float cr[32], ci[32];       // c'
};
static __device__ __forceinline__ void compute_params(
    ModeParams& P, int h, int n,
    const float* __restrict__ log_dt, const float* __restrict__ A_real,
    const float* __restrict__ A_imag, const float* __restrict__ C_real,
    const float* __restrict__ C_imag) {
    int idx = h * Nn + n;
    float dt = expf(log_dt[h]);
    float Ar = -expf(A_real[idx]);
    float Ai = A_imag[idx];
    float ar = Ar * dt, ai = Ai * dt;
    float er = expf(ar);
    float sn, cs;
    sincosf(ai, &sn, &cs);
    float wr = er * cs, wi = er * sn;
    float den = Ar * Ar + Ai * Ai;
    float e1r = wr - 1.0f, e1i = wi;
    float qr = (e1r * Ar + e1i * Ai) / den;
    float qi = (e1i * Ar - e1r * Ai) / den;
    float Cr = C_real[idx], Ci = C_imag[idx];
    P.ar[n] = ar; P.ai[n] = ai;
    P.wr[n] = wr; P.wi[n] = wi;
    P.cr[n] = Cr * qr - Ci * qi;
    P.ci[n] = Cr * qi + Ci * qr;
}

// =====================================================================
// k_transpose: u (b,l,h) fp32 -> V[h][bc][0..128) fp16
// =====================================================================
__global__ void __launch_bounds__(256)
k_transpose(const float* __restrict__ u) {
    int ht = blockIdx.x, c = blockIdx.y, b = blockIdx.z;
    __shared__ __half ts[32][136];
    int lane = threadIdx.x & 31;
    int r = threadIdx.x >> 5;

    const float* up = u + ((size_t)b * Ln + (size_t)c * Tn) * Hn + ht * 32;
#pragma unroll
    for (int j0 = 0; j0 < Tn; j0 += 8) {
        int j = j0 + r;
        ts[lane][j] = __float2half(up[(size_t)j * Hn + lane]);
    }
    __syncthreads();

    int row = threadIdx.x >> 3;
    int ch = threadIdx.x & 7;
    int bc = b * Cc + c;
    __half* dst = g_V + ((size_t)(ht * 32 + row) * BC + bc) * KD;
    reinterpret_cast<uint4*>(dst)[ch] =
        *reinterpret_cast<const uint4*>(&ts[row][ch * 8]);
    reinterpret_cast<uint4*>(dst)[ch + 8] =
        *reinterpret_cast<const uint4*>(&ts[row][(ch + 8) * 8]);
}

// =====================================================================
// k_encode: per-h GEMM  Xl[64,256] = Enc[64,128] @ V_u[256,128]^T
// Enc built inline (w^s direct eval); fused inter-chunk combine
// writes fp16 states into V[..][128..192).
// =====================================================================
#define LDA1 136
#define LDB1 136
#define LDX  258
__global__ void __launch_bounds__(256)
k_encode(const float* __restrict__ log_dt, const float* __restrict__ A_real,
         const float* __restrict__ A_imag, const float* __restrict__ C_real,
         const float* __restrict__ C_imag) {
    int h = blockIdx.x;
    int tid = threadIdx.x;
    extern __shared__ __half sm1[];
    __half* As = sm1;                    // [64][LDA1]
    __half* Bs = sm1 + 64 * LDA1;        // [256][LDB1]  (reused as Xl fp32)
    __shared__ ModeParams P;
    __shared__ float wTr[32], wTi[32];

    // async-load B: 256 rows x first 128 halves of V rows (stride KD)
    {
        const __half* vb = g_V + (size_t)h * BC * KD;
        unsigned bsm = smem_u32(Bs);
        for (int i = tid; i < 256 * 16; i += 256) {
            int row = i >> 4, ch = i & 15;
            cp16(bsm + (unsigned)((row * LDB1 + ch * 8) * 2),
                 vb + (size_t)row * KD + ch * 8);
        }
        cp_commit();
    }
    // params + wT = w^128
    if (tid < 32) {
        compute_params(P, h, tid, log_dt, A_real, A_imag, C_real, C_imag);
        float erT = expf(128.f * P.ar[tid]);
        float snT, csT;
        sincosf(128.f * P.ai[tid], &snT, &csT);
        wTr[tid] = erT * csT; wTi[tid] = erT * snT;
    }
    __syncthreads();

    // Enc inline: warp w covers s = w*16+q, lane = n
    {
        int n = tid & 31, w = tid >> 5;
        float ar = P.ar[n], ai = P.ai[n];
#pragma unroll
        for (int q = 0; q < 16; q++) {
            int s = w * 16 + q;
            float fs = (float)s;
            float er = expf(fs * ar);
            float sn, cs;
            sincosf(fs * ai, &sn, &cs);
            As[n * LDA1 + (127 - s)]        = __float2half(er * cs);
            As[(n + 32) * LDA1 + (127 - s)] = __float2half(er * sn);
        }
    }
    cp_wait_all();
    __syncthreads();

    int wid = tid >> 5, lane = tid & 31;
    int wm = wid & 1, wn = wid >> 1;
    int m_base = wm * 32, n_base = wn * 64;

    float acc[2][8][4];
#pragma unroll
    for (int a = 0; a < 2; a++)
#pragma unroll
        for (int bI = 0; bI < 8; bI++)
#pragma unroll
            for (int cI = 0; cI < 4; cI++) acc[a][bI][cI] = 0.f;

    int la = lane & 15;
    int aRowOff = (lane < 16) ? lane : (lane - 16);
    int aColOff = (lane < 16) ? 0 : 8;
    int bRowOff = la & 7;
    int bColOff = (la >> 3) * 8;

#pragma unroll
    for (int kk = 0; kk < 128; kk += 16) {
        unsigned af[2][4];
#pragma unroll
        for (int mf = 0; mf < 2; mf++) {
            int m0 = m_base + mf * 16;
            unsigned addr = smem_u32(&As[(m0 + aRowOff) * LDA1 + kk + aColOff]);
            ldmA(addr, af[mf][0], af[mf][1], af[mf][2], af[mf][3]);
        }
        unsigned bf[8][2];
#pragma unroll
        for (int nf = 0; nf < 8; nf++) {
            int n0 = n_base + nf * 8;
            unsigned addr = smem_u32(&Bs[(n0 + bRowOff) * LDB1 + kk + bColOff]);
            ldmB(addr, bf[nf][0], bf[nf][1]);
        }
#pragma unroll
        for (int mf = 0; mf < 2; mf++)
#pragma unroll
            for (int nf = 0; nf < 8; nf++)
                mma16816(acc[mf][nf], af[mf], bf[nf]);
    }

    __syncthreads();
    float* Xls = reinterpret_cast<float*>(Bs);
    {
        int r = lane >> 2, cp = lane & 3;
#pragma unroll
        for (int mf = 0; mf < 2; mf++) {
#pragma unroll
            for (int nf = 0; nf < 8; nf++) {
                int m = m_base + mf * 16 + r;
                int n = n_base + nf * 8 + cp * 2;
                *reinterpret_cast<float2*>(&Xls[m * LDX + n]) =
                    make_float2(acc[mf][nf][0], acc[mf][nf][1]);
                *reinterpret_cast<float2*>(&Xls[(m + 8) * LDX + n]) =
                    make_float2(acc[mf][nf][2], acc[mf][nf][3]);
            }
        }
    }
    __syncthreads();

    {
        int n = tid & 31, b = tid >> 5;
        float wtr = wTr[n], wti = wTi[n];
        float XR = 0.f, XI = 0.f;
        __half* vbase = g_V + (size_t)h * BC * KD;
        const float* xR = &Xls[n * LDX];
        const float* xI = &Xls[(n + 32) * LDX];
#pragma unroll 4
        for (int c = 0; c < Cc; c++) {
            int bc = b * Cc + c;
            vbase[(size_t)bc * KD + 128 + n] = __float2half(XR);
            vbase[(size_t)bc * KD + 160 + n] = __float2half(XI);
            float lr = xR[bc], li = xI[bc];
            float nR = wtr * XR - wti * XI + lr;
            float nI = wtr * XI + wti * XR + li;
            XR = nR; XI = nI;
        }
    }
}

// =====================================================================
// k_main: per-(h, s) GEMM  Y[128,128] = [Toep(Ks)|Dec] @ V_tile^T
// A panel built inline (Ks + Dec from closed form), B via cp.async,
// register double-buffered mainloop, triangular k-step skip for m<64.
// =====================================================================
#define LDA2 200
#define LDB2 200
#define LDO  136
__global__ void __launch_bounds__(256, 2)
k_main(const float* __restrict__ log_dt, const float* __restrict__ A_real,
       const float* __restrict__ A_imag, const float* __restrict__ C_real,
       const float* __restrict__ C_imag) {
    int h = blockIdx.x;
    int s = blockIdx.y;
    int tid = threadIdx.x;
    extern __shared__ __half sm2[];
    __half* As = sm2;                     // [128][LDA2]
    __half* Bs = sm2 + 128 * LDA2;        // [128][LDB2]
    __shared__ float Ksh[Tn];
    __shared__ ModeParams P;

    // async-load B tile: 128 rows x 192 halves
    {
        const __half* vb = g_V + ((size_t)h * BC + s * 128) * KD;
        unsigned bsm = smem_u32(Bs);
        for (int i = tid; i < 128 * 24; i += 256) {
            int row = i / 24, ch = i % 24;
            cp16(bsm + (unsigned)((row * LDB2 + ch * 8) * 2),
                 vb + (size_t)row * KD + ch * 8);
        }
        cp_commit();
    }
    if (tid < 32)
        compute_params(P, h, tid, log_dt, A_real, A_imag, C_real, C_imag);
    __syncthreads();

    // Inline Ks + Dec: warp w covers s' = w*16+q, lane = n.
    //   t = c' * w^{s'};  Ks[s'] = 2 sum_n Re(t);  Dec[s'] = 2Re(t*w), -2Im(t*w)
    {
        int n = tid & 31, w = tid >> 5;
        float ar = P.ar[n], ai = P.ai[n];
        float cr = P.cr[n], ci = P.ci[n];
        float wr = P.wr[n], wi = P.wi[n];
#pragma unroll
        for (int q = 0; q < 16; q++) {
            int sp = w * 16 + q;
            float fs = (float)sp;
            float er = expf(fs * ar);
            float sn, cs;
            sincosf(fs * ai, &sn, &cs);
            float pr = er * cs, pi = er * sn;           // w^{s'}
            float tr = cr * pr - ci * pi;
            float ti = cr * pi + ci * pr;               // c' * w^{s'}
            float dr = tr * wr - ti * wi;
            float di = tr * wi + ti * wr;               // c' * w^{s'+1}
            As[sp * LDA2 + 128 + n] = __float2half(2.0f * dr);
            As[sp * LDA2 + 160 + n] = __float2half(-2.0f * di);
            float term = 2.0f * tr;
#pragma unroll
            for (int off = 16; off; off >>= 1)
                term += __shfl_xor_sync(0xffffffffu, term, off);
            if (n == 0) Ksh[sp] = term;
        }
    }
    __syncthreads();
    // vectorized Toeplitz fill (cols 0..127) from Ksh
    for (int i = tid; i < 128 * 16; i += 256) {
        int row = i >> 4, ch = i & 15;
        int j0 = ch * 8;
        __half hv[8];
#pragma unroll
        for (int k = 0; k < 8; k++) {
            int j = j0 + k;
            hv[k] = __float2half((row >= j) ? Ksh[row - j] : 0.f);
        }
        *reinterpret_cast<uint4*>(&As[row * LDA2 + j0]) =
            *reinterpret_cast<const uint4*>(hv);
    }
    cp_wait_all();
    __syncthreads();

    int wid = tid >> 5, lane = tid & 31;
    int wm = wid >> 2, wn = wid & 3;     // balanced: each SMSP gets wm0+wm1
    int m_base = wm * 64, n_base = wn * 32;

    float acc[4][4][4];
#pragma unroll
    for (int a = 0; a < 4; a++)
#pragma unroll
        for (int bI = 0; bI < 4; bI++)
#pragma unroll
            for (int cI = 0; cI < 4; cI++) acc[a][bI][cI] = 0.f;

    int la = lane & 15;
    int aRowOff = (lane < 16) ? lane : (lane - 16);
    int aColOff = (lane < 16) ? 0 : 8;
    int bRowOff = la & 7;
    int bColOff = (la >> 3) * 8;

    unsigned aBase = smem_u32(&As[(m_base + aRowOff) * LDA2 + aColOff]);
    unsigned bBase = smem_u32(&Bs[(n_base + bRowOff) * LDB2 + bColOff]);

    unsigned af[2][4][4];
    unsigned bf[2][4][2];

#define LOAD_AB(buf, ks_)                                                     \
    {                                                                         \
        const int kk_ = (ks_) * 16;                                           \
        _Pragma("unroll")                                                     \
        for (int mf = 0; mf < 4; mf++)                                        \
            ldmA(aBase + (unsigned)((mf * 16 * LDA2 + kk_) * 2),              \
                 af[buf][mf][0], af[buf][mf][1], af[buf][mf][2], af[buf][mf][3]); \
        _Pragma("unroll")                                                     \
        for (int nf = 0; nf < 4; nf++)                                        \
            ldmB(bBase + (unsigned)((nf * 8 * LDB2 + kk_) * 2),               \
                 bf[buf][nf][0], bf[buf][nf][1]);                             \
    }
#define MMA_STEP(buf)                                                         \
    {                                                                         \
        _Pragma("unroll")                                                     \
        for (int mf = 0; mf < 4; mf++)                                        \
            _Pragma("unroll")                                                 \
            for (int nf = 0; nf < 4; nf++)                                    \
                mma16816(acc[mf][nf], af[buf][mf], bf[buf][nf]);              \
    }

    if (wm == 0) {
        // Toeplitz block all-zero for j>=64 when i<64: k-steps {0,1,2,3,8,9,10,11}
        LOAD_AB(0, 0)
#pragma unroll
        for (int it = 0; it < 8; it++) {
            int cur = it & 1;
            if (it < 7) {
                int nks = (it + 1 < 4) ? (it + 1) : (it + 5);
                LOAD_AB(cur ^ 1, nks)
            }
            MMA_STEP(cur)
        }
    } else {
        LOAD_AB(0, 0)
#pragma unroll
        for (int it = 0; it < 12; it++) {
            int cur = it & 1;
            if (it < 11) LOAD_AB(cur ^ 1, it + 1)
            MMA_STEP(cur)
        }
    }
#undef LOAD_AB
#undef MMA_STEP

    // stage output [128 bc][128 m] fp16 in smem (reuse As), coalesced store
    __syncthreads();
    __half* ot = As;
    {
        int r = lane >> 2, cp = lane & 3;
#pragma unroll
        for (int mf = 0; mf < 4; mf++) {
            int m = m_base + mf * 16 + r;
#pragma unroll
            for (int nf = 0; nf < 4; nf++) {
                int n = n_base + nf * 8 + cp * 2;
                ot[n * LDO + m]           = __float2half(acc[mf][nf][0]);
                ot[(n + 1) * LDO + m]     = __float2half(acc[mf][nf][1]);
                ot[n * LDO + m + 8]       = __float2half(acc[mf][nf][2]);
                ot[(n + 1) * LDO + m + 8] = __float2half(acc[mf][nf][3]);
            }
        }
    }
    __syncthreads();
    {
        __half* dst = g_yT16 + ((size_t)h * BC + s * 128) * Tn;
        for (int i = tid; i < 128 * 16; i += 256) {
            int row = i >> 4, ch = i & 15;
            *reinterpret_cast<uint4*>(&dst[row * Tn + ch * 8]) =
                *reinterpret_cast<const uint4*>(&ot[row * LDO + ch * 8]);
        }
    }
}

// =====================================================================
// k_final: transpose yT16 -> (b,l,h), + D*u (skipped when D==0), GELU
// =====================================================================
__global__ void __launch_bounds__(256)
k_final(const float* __restrict__ u, const float* __restrict__ Dp,
        float* __restrict__ out) {
    int ht = blockIdx.x, c = blockIdx.y, b = blockIdx.z;
    __shared__ float ys[128][33];
    int bc = b * Cc + c;

    {
#pragma unroll
        for (int q = 0; q < 2; q++) {
            int idx = threadIdx.x + q * 256;
            int row = idx >> 4;
            int ch = idx & 15;
            const uint4* src = reinterpret_cast<const uint4*>(
                g_yT16 + ((size_t)(ht * 32 + row) * BC + bc) * Tn);
            uint4 v = src[ch];
            const __half* hp = reinterpret_cast<const __half*>(&v);
            int i = ch * 8;
#pragma unroll
            for (int k = 0; k < 8; k++)
                ys[i + k][row] = __half2float(hp[k]);
        }
    }
    __syncthreads();

    float Dv = *Dp;
    int lane = threadIdx.x & 31;
    int r = threadIdx.x >> 5;
    if (Dv != 0.0f) {
#pragma unroll
        for (int i0 = 0; i0 < Tn; i0 += 8) {
            int i = i0 + r;
            size_t gidx = ((size_t)b * Ln + (size_t)c * Tn + i) * Hn + ht * 32 + lane;
            float v = ys[i][lane] + Dv * u[gidx];
            out[gidx] = gelu_erf(v);
        }
    } else {
#pragma unroll
        for (int i0 = 0; i0 < Tn; i0 += 8) {
            int i = i0 + r;
            size_t gidx = ((size_t)b * Ln + (size_t)c * Tn + i) * Hn + ht * 32 + lane;
            out[gidx] = gelu_erf(ys[i][lane]);
        }
    }
}

// =====================================================================
// launch
// =====================================================================
extern "C" void kernel_launch(void* const* d_in, const int* in_sizes, int n_in,
                              void* d_out, int out_size) {
    (void)in_sizes; (void)n_in; (void)out_size;
    const float* u      = (const float*)d_in[0];
    const float* log_dt = (const float*)d_in[1];
    const float* A_real = (const float*)d_in[2];
    const float* A_imag = (const float*)d_in[3];
    const float* C_real = (const float*)d_in[4];
    const float* C_imag = (const float*)d_in[5];
    const float* D      = (const float*)d_in[6];
    float* out = (float*)d_out;

    static bool attr_done = false;
    if (!attr_done) {
        cudaFuncSetAttribute(k_encode, cudaFuncAttributeMaxDynamicSharedMemorySize,
                             (64 * LDA1 + 256 * LDB1) * 2);
        cudaFuncSetAttribute(k_main, cudaFuncAttributeMaxDynamicSharedMemorySize,
                             (128 * LDA2 + 128 * LDB2) * 2);
        attr_done = true;
    }

    k_transpose<<<dim3(Hn / 32, Cc, Bn), 256>>>(u);
    k_encode<<<Hn, 256, (64 * LDA1 + 256 * LDB1) * 2>>>(
        log_dt, A_real, A_imag, C_real, C_imag);
    k_main<<<dim3(Hn, 2), 256, (128 * LDA2 + 128 * LDB2) * 2>>>(
        log_dt, A_real, A_imag, C_real, C_imag);
    k_final<<<dim3(Hn / 32, Cc, Bn), 256>>>(u, D, out);
}

// round 7
// speedup vs baseline: 3.1302x; 1.1417x over previous
#include <cuda_runtime.h>
#include <cuda_fp16.h>
#include <math.h>

// Problem constants
#define Bn 8
#define Ln 4096
#define Hn 1024
#define Nn 32
#define Tn 128            // chunk length
#define Cc 32             // chunks (Tn*Cc == Ln)
#define BC 256            // B*C columns
#define KD 192            // main GEMM K dim: 128 (u) + 64 (states)

// ---- persistent device buffers (no allocs allowed) ----
__device__ __align__(256) __half  g_V[(size_t)Hn * BC * 128];  // per-h u operand [256][128]
__device__ __align__(256) __half  g_yT16[(size_t)Hn * BC * Tn];// per-h output [256][128] fp16

// ---- small helpers ----
static __device__ __forceinline__ unsigned smem_u32(const void* p) {
    unsigned r;
    asm("{ .reg .u64 t; cvta.to.shared.u64 t, %1; cvt.u32.u64 %0, t; }"
        : "=r"(r) : "l"(p));
    return r;
}
static __device__ __forceinline__ void cp16(unsigned dst, const void* src) {
    asm volatile("cp.async.cg.shared.global [%0], [%1], 16;" :: "r"(dst), "l"(src));
}
static __device__ __forceinline__ void cp_commit() {
    asm volatile("cp.async.commit_group;");
}
static __device__ __forceinline__ void cp_wait_all() {
    asm volatile("cp.async.wait_group 0;");
}
static __device__ __forceinline__ void ldmA(unsigned addr, unsigned& r0, unsigned& r1,
                                            unsigned& r2, unsigned& r3) {
    asm volatile("ldmatrix.sync.aligned.m8n8.x4.shared.b16 {%0,%1,%2,%3}, [%4];"
                 : "=r"(r0), "=r"(r1), "=r"(r2), "=r"(r3) : "r"(addr));
}
static __device__ __forceinline__ void ldmB(unsigned addr, unsigned& r0, unsigned& r1) {
    asm volatile("ldmatrix.sync.aligned.m8n8.x2.shared.b16 {%0,%1}, [%2];"
                 : "=r"(r0), "=r"(r1) : "r"(addr));
}
static __device__ __forceinline__ void mma16816(float* d, const unsigned* a,
                                                const unsigned* b) {
    asm volatile(
        "mma.sync.aligned.m16n8k16.row.col.f32.f16.f16.f32 "
        "{%0,%1,%2,%3}, {%4,%5,%6,%7}, {%8,%9}, {%0,%1,%2,%3};"
        : "+f"(d[0]), "+f"(d[1]), "+f"(d[2]), "+f"(d[3])
        : "r"(a[0]), "r"(a[1]), "r"(a[2]), "r"(a[3]), "r"(b[0]), "r"(b[1]));
}

// Fast branch-free erf-GELU (A&S 7.1.26, |eps_erf| < 1.5e-7)
static __device__ __forceinline__ float gelu_erf(float v) {
    float z = fabsf(v) * 0.70710678118654752440f;
    float t = __fdividef(1.0f, fmaf(0.3275911f, z, 1.0f));
    float p = fmaf(1.061405429f, t, -1.453152027f);
    p = fmaf(p, t, 1.421413741f);
    p = fmaf(p, t, -0.284496736f);
    p = fmaf(p, t, 0.254829592f);
    p *= t;
    float e = __expf(-z * z);
    float erfz = fmaf(-p, e, 1.0f);          // erf(|v|/sqrt2)
    float erfv = copysignf(erfz, v);
    return 0.5f * v * (1.0f + erfv);
}

// Per-mode recurrence params: w = exp(dt*A), c' = C*(w-1)/A
struct ModeParams {
    float ar[32], ai[32];       // log|w|, arg w
    float wr[32], wi[32];       // w
    float cr[32], ci[32];       // c'
};
static __device__ __forceinline__ void compute_params(
    ModeParams& P, int h, int n,
    const float* __restrict__ log_dt, const float* __restrict__ A_real,
    const float* __restrict__ A_imag, const float* __restrict__ C_real,
    const float* __restrict__ C_imag) {
    int idx = h * Nn + n;
    float dt = expf(log_dt[h]);
    float Ar = -expf(A_real[idx]);
    float Ai = A_imag[idx];
    float ar = Ar * dt, ai = Ai * dt;
    float er = expf(ar);
    float sn, cs;
    sincosf(ai, &sn, &cs);
    float wr = er * cs, wi = er * sn;
    float den = Ar * Ar + Ai * Ai;
    float e1r = wr - 1.0f, e1i = wi;
    float qr = (e1r * Ar + e1i * Ai) / den;
    float qi = (e1i * Ar - e1r * Ai) / den;
    float Cr = C_real[idx], Ci = C_imag[idx];
    P.ar[n] = ar; P.ai[n] = ai;
    P.wr[n] = wr; P.wi[n] = wi;
    P.cr[n] = Cr * qr - Ci * qi;
    P.ci[n] = Cr * qi + Ci * qr;
}

// =====================================================================
// k_transpose: u (b,l,h) fp32 -> g_V[h][bc][0..128) fp16
// =====================================================================
__global__ void __launch_bounds__(256)
k_transpose(const float* __restrict__ u) {
    int ht = blockIdx.x, c = blockIdx.y, b = blockIdx.z;
    __shared__ __half ts[32][136];
    int lane = threadIdx.x & 31;
    int r = threadIdx.x >> 5;

    const float* up = u + ((size_t)b * Ln + (size_t)c * Tn) * Hn + ht * 32;
#pragma unroll
    for (int j0 = 0; j0 < Tn; j0 += 8) {
        int j = j0 + r;
        ts[lane][j] = __float2half(up[(size_t)j * Hn + lane]);
    }
    __syncthreads();

    int row = threadIdx.x >> 3;
    int ch = threadIdx.x & 7;
    int bc = b * Cc + c;
    __half* dst = g_V + ((size_t)(ht * 32 + row) * BC + bc) * 128;
    reinterpret_cast<uint4*>(dst)[ch] =
        *reinterpret_cast<const uint4*>(&ts[row][ch * 8]);
    reinterpret_cast<uint4*>(dst)[ch + 8] =
        *reinterpret_cast<const uint4*>(&ts[row][(ch + 8) * 8]);
}

// =====================================================================
// k_fused: one block per h.
//   phase 1: cp.async u-tile [256][128] -> Bs cols 0..127
//   phase 2: inline Enc; encode GEMM -> Xl[64][256]
//   phase 3: combine -> fp16 states into Bs cols 128..191 (smem only)
//   phase 4: inline A panel [Toep(Ks)|Dec]; main GEMM in 2 bc-rounds
//   phase 5: epilogue -> g_yT16[h][bc][m] fp16 coalesced
// =====================================================================
#define LDB  200     // Bs row stride (halves)
#define LDA1 136     // Enc row stride
#define LDX  258     // Xl fp32 row stride
#define LDA2 200     // main A row stride
#define LDO  136     // epilogue staging stride
#define R1_OFF (256 * LDB)                    // halves
#define SMEM_FUSED ((256 * LDB) * 2 + 66048)  // bytes

__global__ void __launch_bounds__(256, 1)
k_fused(const float* __restrict__ log_dt, const float* __restrict__ A_real,
        const float* __restrict__ A_imag, const float* __restrict__ C_real,
        const float* __restrict__ C_imag) {
    int h = blockIdx.x;
    int tid = threadIdx.x;
    extern __shared__ __half sm[];
    __half* Bs = sm;                 // [256][LDB]
    __half* R1 = sm + R1_OFF;        // 66048B scratch: Enc / Xl / A / —
    __shared__ ModeParams P;
    __shared__ float wTr[32], wTi[32], Ksh[Tn];

    // ---- phase 1: async u-tile ----
    {
        const __half* vb = g_V + (size_t)h * BC * 128;
        unsigned bsm = smem_u32(Bs);
        for (int i = tid; i < 256 * 16; i += 256) {
            int row = i >> 4, ch = i & 15;
            cp16(bsm + (unsigned)((row * LDB + ch * 8) * 2),
                 vb + (size_t)row * 128 + ch * 8);
        }
        cp_commit();
    }
    if (tid < 32) {
        compute_params(P, h, tid, log_dt, A_real, A_imag, C_real, C_imag);
        float erT = expf(128.f * P.ar[tid]);
        float snT, csT;
        sincosf(128.f * P.ai[tid], &snT, &csT);
        wTr[tid] = erT * csT; wTi[tid] = erT * snT;
    }
    __syncthreads();

    // ---- phase 2a: inline Enc into R1 ----
    __half* EncS = R1;
    {
        int n = tid & 31, w = tid >> 5;
        float ar = P.ar[n], ai = P.ai[n];
#pragma unroll
        for (int q = 0; q < 16; q++) {
            int s = w * 16 + q;
            float fs = (float)s;
            float er = __expf(fs * ar);
            float sn, cs;
            sincosf(fs * ai, &sn, &cs);
            EncS[n * LDA1 + (127 - s)]        = __float2half(er * cs);
            EncS[(n + 32) * LDA1 + (127 - s)] = __float2half(er * sn);
        }
    }
    cp_wait_all();
    __syncthreads();

    int wid = tid >> 5, lane = tid & 31;
    int la = lane & 15;
    int aRowOff = (lane < 16) ? lane : (lane - 16);
    int aColOff = (lane < 16) ? 0 : 8;
    int bRowOff = la & 7;
    int bColOff = (la >> 3) * 8;

    // ---- phase 2b: encode GEMM  Xl[64,256] = Enc @ B_u^T ----
    {
        int wm = wid & 1, wn = wid >> 1;
        int m_base = wm * 32, n_base = wn * 64;

        float acc[2][8][4];
#pragma unroll
        for (int a = 0; a < 2; a++)
#pragma unroll
            for (int bI = 0; bI < 8; bI++)
#pragma unroll
                for (int cI = 0; cI < 4; cI++) acc[a][bI][cI] = 0.f;

#pragma unroll
        for (int kk = 0; kk < 128; kk += 16) {
            unsigned af[2][4];
#pragma unroll
            for (int mf = 0; mf < 2; mf++) {
                int m0 = m_base + mf * 16;
                unsigned addr = smem_u32(&EncS[(m0 + aRowOff) * LDA1 + kk + aColOff]);
                ldmA(addr, af[mf][0], af[mf][1], af[mf][2], af[mf][3]);
            }
            unsigned bf[8][2];
#pragma unroll
            for (int nf = 0; nf < 8; nf++) {
                int n0 = n_base + nf * 8;
                unsigned addr = smem_u32(&Bs[(n0 + bRowOff) * LDB + kk + bColOff]);
                ldmB(addr, bf[nf][0], bf[nf][1]);
            }
#pragma unroll
            for (int mf = 0; mf < 2; mf++)
#pragma unroll
                for (int nf = 0; nf < 8; nf++)
                    mma16816(acc[mf][nf], af[mf], bf[nf]);
        }
        __syncthreads();   // Enc reads done -> reuse R1 as Xl

        float* Xls = reinterpret_cast<float*>(R1);
        int r = lane >> 2, cp = lane & 3;
#pragma unroll
        for (int mf = 0; mf < 2; mf++) {
#pragma unroll
            for (int nf = 0; nf < 8; nf++) {
                int m = m_base + mf * 16 + r;
                int n = n_base + nf * 8 + cp * 2;
                *reinterpret_cast<float2*>(&Xls[m * LDX + n]) =
                    make_float2(acc[mf][nf][0], acc[mf][nf][1]);
                *reinterpret_cast<float2*>(&Xls[(m + 8) * LDX + n]) =
                    make_float2(acc[mf][nf][2], acc[mf][nf][3]);
            }
        }
    }
    __syncthreads();

    // ---- phase 3: combine -> fp16 states into Bs cols [128..192) ----
    {
        const float* Xls = reinterpret_cast<const float*>(R1);
        int n = tid & 31, b = tid >> 5;
        float wtr = wTr[n], wti = wTi[n];
        float XR = 0.f, XI = 0.f;
        const float* xR = &Xls[n * LDX];
        const float* xI = &Xls[(n + 32) * LDX];
#pragma unroll 4
        for (int c = 0; c < Cc; c++) {
            int bc = b * Cc + c;
            Bs[bc * LDB + 128 + n] = __float2half(XR);
            Bs[bc * LDB + 160 + n] = __float2half(XI);
            float lr = xR[bc], li = xI[bc];
            float nR = wtr * XR - wti * XI + lr;
            float nI = wtr * XI + wti * XR + li;
            XR = nR; XI = nI;
        }
    }
    __syncthreads();   // Xl reads done -> reuse R1 as A panel

    // ---- phase 4a: inline A panel (Dec + Ks, then Toeplitz) ----
    __half* As = R1;
    {
        int n = tid & 31, w = tid >> 5;
        float ar = P.ar[n], ai = P.ai[n];
        float cr = P.cr[n], ci = P.ci[n];
        float wr = P.wr[n], wi = P.wi[n];
#pragma unroll
        for (int q = 0; q < 16; q++) {
            int sp = w * 16 + q;
            float fs = (float)sp;
            float er = __expf(fs * ar);
            float sn, cs;
            sincosf(fs * ai, &sn, &cs);
            float pr = er * cs, pi = er * sn;           // w^{s'}
            float tr = cr * pr - ci * pi;
            float ti = cr * pi + ci * pr;               // c' w^{s'}
            float dr = tr * wr - ti * wi;
            float di = tr * wi + ti * wr;               // c' w^{s'+1}
            As[sp * LDA2 + 128 + n] = __float2half(2.0f * dr);
            As[sp * LDA2 + 160 + n] = __float2half(-2.0f * di);
            float term = 2.0f * tr;
#pragma unroll
            for (int off = 16; off; off >>= 1)
                term += __shfl_xor_sync(0xffffffffu, term, off);
            if (n == 0) Ksh[sp] = term;
        }
    }
    __syncthreads();
    for (int i = tid; i < 128 * 16; i += 256) {
        int row = i >> 4, ch = i & 15;
        int j0 = ch * 8;
        __half hv[8];
#pragma unroll
        for (int k = 0; k < 8; k++) {
            int j = j0 + k;
            hv[k] = __float2half((row >= j) ? Ksh[row - j] : 0.f);
        }
        *reinterpret_cast<uint4*>(&As[row * LDA2 + j0]) =
            *reinterpret_cast<const uint4*>(hv);
    }
    __syncthreads();

    // ---- phase 4b/5: main GEMM, 2 bc-rounds, epilogue each ----
    int wm = wid >> 2, wn2 = wid & 3;    // balanced short/long warps per SMSP
    int m_base = wm * 64, n_base = wn2 * 32;
    unsigned aBase = smem_u32(&As[(m_base + aRowOff) * LDA2 + aColOff]);

#pragma unroll
    for (int s2 = 0; s2 < 2; s2++) {
        unsigned bBase = smem_u32(&Bs[(s2 * 128 + n_base + bRowOff) * LDB + bColOff]);

        float acc[4][4][4];
#pragma unroll
        for (int a = 0; a < 4; a++)
#pragma unroll
            for (int bI = 0; bI < 4; bI++)
#pragma unroll
                for (int cI = 0; cI < 4; cI++) acc[a][bI][cI] = 0.f;

        unsigned af[2][4][4];
        unsigned bf[2][4][2];

#define LOAD_AB(buf, ks_)                                                     \
    {                                                                         \
        const int kk_ = (ks_) * 16;                                           \
        _Pragma("unroll")                                                     \
        for (int mf = 0; mf < 4; mf++)                                        \
            ldmA(aBase + (unsigned)((mf * 16 * LDA2 + kk_) * 2),              \
                 af[buf][mf][0], af[buf][mf][1], af[buf][mf][2], af[buf][mf][3]); \
        _Pragma("unroll")                                                     \
        for (int nf = 0; nf < 4; nf++)                                        \
            ldmB(bBase + (unsigned)((nf * 8 * LDB + kk_) * 2),                \
                 bf[buf][nf][0], bf[buf][nf][1]);                             \
    }
#define MMA_STEP(buf)                                                         \
    {                                                                         \
        _Pragma("unroll")                                                     \
        for (int mf = 0; mf < 4; mf++)                                        \
            _Pragma("unroll")                                                 \
            for (int nf = 0; nf < 4; nf++)                                    \
                mma16816(acc[mf][nf], af[buf][mf], bf[buf][nf]);              \
    }

        if (wm == 0) {
            // rows m<64: Toeplitz cols 64..127 are zero -> k-steps {0..3, 8..11}
            LOAD_AB(0, 0)
#pragma unroll
            for (int it = 0; it < 8; it++) {
                int cur = it & 1;
                if (it < 7) {
                    int nks = (it + 1 < 4) ? (it + 1) : (it + 5);
                    LOAD_AB(cur ^ 1, nks)
                }
                MMA_STEP(cur)
            }
        } else {
            LOAD_AB(0, 0)
#pragma unroll
            for (int it = 0; it < 12; it++) {
                int cur = it & 1;
                if (it < 11) LOAD_AB(cur ^ 1, it + 1)
                MMA_STEP(cur)
            }
        }
#undef LOAD_AB
#undef MMA_STEP

        // epilogue: stage [128 bc][128 m] fp16 into Bs rows 0..127 region
        __syncthreads();   // GEMM reads of this round done (also covers prev STG reads)
        __half* ot = Bs;   // 34816B <= 51200B (rows 0..127 footprint)
        {
            int r = lane >> 2, cp = lane & 3;
#pragma unroll
            for (int mf = 0; mf < 4; mf++) {
                int m = m_base + mf * 16 + r;
#pragma unroll
                for (int nf = 0; nf < 4; nf++) {
                    int n = n_base + nf * 8 + cp * 2;
                    ot[n * LDO + m]           = __float2half(acc[mf][nf][0]);
                    ot[(n + 1) * LDO + m]     = __float2half(acc[mf][nf][1]);
                    ot[n * LDO + m + 8]       = __float2half(acc[mf][nf][2]);
                    ot[(n + 1) * LDO + m + 8] = __float2half(acc[mf][nf][3]);
                }
            }
        }
        __syncthreads();
        {
            __half* dst = g_yT16 + ((size_t)h * BC + s2 * 128) * Tn;
            for (int i = tid; i < 128 * 16; i += 256) {
                int row = i >> 4, ch = i & 15;
                *reinterpret_cast<uint4*>(&dst[row * Tn + ch * 8]) =
                    *reinterpret_cast<const uint4*>(&ot[row * LDO + ch * 8]);
            }
        }
    }
}

// =====================================================================
// k_final: transpose yT16 -> (b,l,h), + D*u (skipped when D==0), GELU
// =====================================================================
__global__ void __launch_bounds__(256)
k_final(const float* __restrict__ u, const float* __restrict__ Dp,
        float* __restrict__ out) {
    int ht = blockIdx.x, c = blockIdx.y, b = blockIdx.z;
    __shared__ float ys[128][33];
    int bc = b * Cc + c;

    {
#pragma unroll
        for (int q = 0; q < 2; q++) {
            int idx = threadIdx.x + q * 256;
            int row = idx >> 4;
            int ch = idx & 15;
            const uint4* src = reinterpret_cast<const uint4*>(
                g_yT16 + ((size_t)(ht * 32 + row) * BC + bc) * Tn);
            uint4 v = src[ch];
            const __half* hp = reinterpret_cast<const __half*>(&v);
            int i = ch * 8;
#pragma unroll
            for (int k = 0; k < 8; k++)
                ys[i + k][row] = __half2float(hp[k]);
        }
    }
    __syncthreads();

    float Dv = *Dp;
    int lane = threadIdx.x & 31;
    int r = threadIdx.x >> 5;
    size_t base = ((size_t)b * Ln + (size_t)c * Tn + r) * Hn + ht * 32 + lane;
    if (Dv != 0.0f) {
#pragma unroll
        for (int i0 = 0; i0 < Tn; i0 += 8) {
            int i = i0 + r;
            size_t gidx = base + (size_t)i0 * Hn;
            float v = ys[i][lane] + Dv * u[gidx];
            out[gidx] = gelu_erf(v);
        }
    } else {
#pragma unroll
        for (int i0 = 0; i0 < Tn; i0 += 8) {
            int i = i0 + r;
            size_t gidx = base + (size_t)i0 * Hn;
            out[gidx] = gelu_erf(ys[i][lane]);
        }
    }
}

// =====================================================================
// launch
// =====================================================================
extern "C" void kernel_launch(void* const* d_in, const int* in_sizes, int n_in,
                              void* d_out, int out_size) {
    (void)in_sizes; (void)n_in; (void)out_size;
    const float* u      = (const float*)d_in[0];
    const float* log_dt = (const float*)d_in[1];
    const float* A_real = (const float*)d_in[2];
    const float* A_imag = (const float*)d_in[3];
    const float* C_real = (const float*)d_in[4];
    const float* C_imag = (const float*)d_in[5];
    const float* D      = (const float*)d_in[6];
    float* out = (float*)d_out;

    static bool attr_done = false;
    if (!attr_done) {
        cudaFuncSetAttribute(k_fused, cudaFuncAttributeMaxDynamicSharedMemorySize,
                             SMEM_FUSED);
        attr_done = true;
    }

    k_transpose<<<dim3(Hn / 32, Cc, Bn), 256>>>(u);
    k_fused<<<Hn, 256, SMEM_FUSED>>>(log_dt, A_real, A_imag, C_real, C_imag);
    k_final<<<dim3(Hn / 32, Cc, Bn), 256>>>(u, D, out);
}

// round 8
// speedup vs baseline: 3.1729x; 1.0136x over previous
#include <cuda_runtime.h>
#include <cuda_fp16.h>
#include <math.h>

// Problem constants
#define Bn 8
#define Ln 4096
#define Hn 1024
#define Nn 32
#define Tn 128            // chunk length
#define Cc 32             // chunks (Tn*Cc == Ln)
#define BC 256            // B*C columns
#define KD 192            // main GEMM K dim: 128 (u) + 64 (states)

// ---- persistent device buffers (no allocs allowed) ----
__device__ __align__(256) __half  g_V[(size_t)Hn * BC * 128];  // per-h u operand [256][128]
__device__ __align__(256) __half  g_yT16[(size_t)Hn * BC * Tn];// per-h output [256][128] fp16

// ---- small helpers ----
static __device__ __forceinline__ unsigned smem_u32(const void* p) {
    unsigned r;
    asm("{ .reg .u64 t; cvta.to.shared.u64 t, %1; cvt.u32.u64 %0, t; }"
        : "=r"(r) : "l"(p));
    return r;
}
static __device__ __forceinline__ void cp16(unsigned dst, const void* src) {
    asm volatile("cp.async.cg.shared.global [%0], [%1], 16;" :: "r"(dst), "l"(src));
}
static __device__ __forceinline__ void cp_commit() {
    asm volatile("cp.async.commit_group;");
}
static __device__ __forceinline__ void cp_wait_all() {
    asm volatile("cp.async.wait_group 0;");
}
static __device__ __forceinline__ void ldmA(unsigned addr, unsigned& r0, unsigned& r1,
                                            unsigned& r2, unsigned& r3) {
    asm volatile("ldmatrix.sync.aligned.m8n8.x4.shared.b16 {%0,%1,%2,%3}, [%4];"
                 : "=r"(r0), "=r"(r1), "=r"(r2), "=r"(r3) : "r"(addr));
}
static __device__ __forceinline__ void ldmB(unsigned addr, unsigned& r0, unsigned& r1) {
    asm volatile("ldmatrix.sync.aligned.m8n8.x2.shared.b16 {%0,%1}, [%2];"
                 : "=r"(r0), "=r"(r1) : "r"(addr));
}
static __device__ __forceinline__ void mma16816(float* d, const unsigned* a,
                                                const unsigned* b) {
    asm volatile(
        "mma.sync.aligned.m16n8k16.row.col.f32.f16.f16.f32 "
        "{%0,%1,%2,%3}, {%4,%5,%6,%7}, {%8,%9}, {%0,%1,%2,%3};"
        : "+f"(d[0]), "+f"(d[1]), "+f"(d[2]), "+f"(d[3])
        : "r"(a[0]), "r"(a[1]), "r"(a[2]), "r"(a[3]), "r"(b[0]), "r"(b[1]));
}

// Fast branch-free erf-GELU (A&S 7.1.26, |eps_erf| < 1.5e-7)
static __device__ __forceinline__ float gelu_erf(float v) {
    float z = fabsf(v) * 0.70710678118654752440f;
    float t = __fdividef(1.0f, fmaf(0.3275911f, z, 1.0f));
    float p = fmaf(1.061405429f, t, -1.453152027f);
    p = fmaf(p, t, 1.421413741f);
    p = fmaf(p, t, -0.284496736f);
    p = fmaf(p, t, 0.254829592f);
    p *= t;
    float e = __expf(-z * z);
    float erfz = fmaf(-p, e, 1.0f);          // erf(|v|/sqrt2)
    float erfv = copysignf(erfz, v);
    return 0.5f * v * (1.0f + erfv);
}

// Per-mode recurrence params: w = exp(dt*A), c' = C*(w-1)/A
struct ModeParams {
    float ar[32], ai[32];       // log|w|, arg w
    float wr[32], wi[32];       // w
    float cr[32], ci[32];       // c'
};
static __device__ __forceinline__ void compute_params(
    ModeParams& P, int h, int n,
    const float* __restrict__ log_dt, const float* __restrict__ A_real,
    const float* __restrict__ A_imag, const float* __restrict__ C_real,
    const float* __restrict__ C_imag) {
    int idx = h * Nn + n;
    float dt = expf(log_dt[h]);
    float Ar = -expf(A_real[idx]);
    float Ai = A_imag[idx];
    float ar = Ar * dt, ai = Ai * dt;
    float er = expf(ar);
    float sn, cs;
    sincosf(ai, &sn, &cs);
    float wr = er * cs, wi = er * sn;
    float den = Ar * Ar + Ai * Ai;
    float e1r = wr - 1.0f, e1i = wi;
    float qr = (e1r * Ar + e1i * Ai) / den;
    float qi = (e1i * Ar - e1r * Ai) / den;
    float Cr = C_real[idx], Ci = C_imag[idx];
    P.ar[n] = ar; P.ai[n] = ai;
    P.wr[n] = wr; P.wi[n] = wi;
    P.cr[n] = Cr * qr - Ci * qi;
    P.ci[n] = Cr * qi + Ci * qr;
}

// =====================================================================
// k_transpose: u (b,l,h) fp32 -> g_V[h][bc][0..128) fp16
// =====================================================================
__global__ void __launch_bounds__(256)
k_transpose(const float* __restrict__ u) {
    int ht = blockIdx.x, c = blockIdx.y, b = blockIdx.z;
    __shared__ __half ts[32][136];
    int lane = threadIdx.x & 31;
    int r = threadIdx.x >> 5;

    const float* up = u + ((size_t)b * Ln + (size_t)c * Tn) * Hn + ht * 32;
#pragma unroll
    for (int j0 = 0; j0 < Tn; j0 += 8) {
        int j = j0 + r;
        ts[lane][j] = __float2half(up[(size_t)j * Hn + lane]);
    }
    __syncthreads();

    int row = threadIdx.x >> 3;
    int ch = threadIdx.x & 7;
    int bc = b * Cc + c;
    __half* dst = g_V + ((size_t)(ht * 32 + row) * BC + bc) * 128;
    reinterpret_cast<uint4*>(dst)[ch] =
        *reinterpret_cast<const uint4*>(&ts[row][ch * 8]);
    reinterpret_cast<uint4*>(dst)[ch + 8] =
        *reinterpret_cast<const uint4*>(&ts[row][(ch + 8) * 8]);
}

// =====================================================================
// k_fused: one block per (h, batch-half). Half = 4 sequences = 128 bc.
//   phase 1: cp.async u-tile [128][128] -> Bs cols 0..127
//   phase 2: inline Enc; encode GEMM -> Xl[64][128]
//   phase 3: combine (4 seqs) -> fp16 states into Bs cols 128..191
//   phase 4: inline A panel [Toep(Ks)|Dec]; main GEMM 128x128x192
//   phase 5: epilogue -> g_yT16[h][half*128+bc][m] fp16 coalesced
// 102.4KB smem -> 2 CTAs/SM.
// =====================================================================
#define LDB  200     // Bs row stride (halves)
#define LDA1 136     // Enc row stride
#define LDX  130     // Xl fp32 row stride
#define LDA2 200     // main A row stride
#define LDO  136     // epilogue staging stride
#define R1_OFF (128 * LDB)                    // halves
#define SMEM_FUSED ((128 * LDB) * 2 + 51200)  // bytes = 102400

__global__ void __launch_bounds__(256, 2)
k_fused(const float* __restrict__ log_dt, const float* __restrict__ A_real,
        const float* __restrict__ A_imag, const float* __restrict__ C_real,
        const float* __restrict__ C_imag) {
    int h = blockIdx.x;
    int half = blockIdx.y;
    int tid = threadIdx.x;
    extern __shared__ __half sm[];
    __half* Bs = sm;                 // [128][LDB]
    __half* R1 = sm + R1_OFF;        // 51200B scratch: Enc / Xl / A / epilogue
    __shared__ ModeParams P;
    __shared__ float wTr[32], wTi[32], Ksh[Tn];

    // ---- phase 1: async u-tile (128 bc rows of this half) ----
    {
        const __half* vb = g_V + ((size_t)h * BC + half * 128) * 128;
        unsigned bsm = smem_u32(Bs);
        for (int i = tid; i < 128 * 16; i += 256) {
            int row = i >> 4, ch = i & 15;
            cp16(bsm + (unsigned)((row * LDB + ch * 8) * 2),
                 vb + (size_t)row * 128 + ch * 8);
        }
        cp_commit();
    }
    if (tid < 32) {
        compute_params(P, h, tid, log_dt, A_real, A_imag, C_real, C_imag);
        float erT = expf(128.f * P.ar[tid]);
        float snT, csT;
        sincosf(128.f * P.ai[tid], &snT, &csT);
        wTr[tid] = erT * csT; wTi[tid] = erT * snT;
    }
    __syncthreads();

    // ---- phase 2a: inline Enc into R1 ----
    __half* EncS = R1;
    {
        int n = tid & 31, w = tid >> 5;
        float ar = P.ar[n], ai = P.ai[n];
#pragma unroll
        for (int q = 0; q < 16; q++) {
            int s = w * 16 + q;
            float fs = (float)s;
            float er = __expf(fs * ar);
            float sn, cs;
            sincosf(fs * ai, &sn, &cs);
            EncS[n * LDA1 + (127 - s)]        = __float2half(er * cs);
            EncS[(n + 32) * LDA1 + (127 - s)] = __float2half(er * sn);
        }
    }
    cp_wait_all();
    __syncthreads();

    int wid = tid >> 5, lane = tid & 31;
    int la = lane & 15;
    int aRowOff = (lane < 16) ? lane : (lane - 16);
    int aColOff = (lane < 16) ? 0 : 8;
    int bRowOff = la & 7;
    int bColOff = (la >> 3) * 8;

    // ---- phase 2b: encode GEMM  Xl[64,128] = Enc @ B_u^T ----
    {
        int wm = wid & 1, wn = wid >> 1;
        int m_base = wm * 32, n_base = wn * 32;

        float acc[2][4][4];
#pragma unroll
        for (int a = 0; a < 2; a++)
#pragma unroll
            for (int bI = 0; bI < 4; bI++)
#pragma unroll
                for (int cI = 0; cI < 4; cI++) acc[a][bI][cI] = 0.f;

#pragma unroll
        for (int kk = 0; kk < 128; kk += 16) {
            unsigned af[2][4];
#pragma unroll
            for (int mf = 0; mf < 2; mf++) {
                int m0 = m_base + mf * 16;
                unsigned addr = smem_u32(&EncS[(m0 + aRowOff) * LDA1 + kk + aColOff]);
                ldmA(addr, af[mf][0], af[mf][1], af[mf][2], af[mf][3]);
            }
            unsigned bf[4][2];
#pragma unroll
            for (int nf = 0; nf < 4; nf++) {
                int n0 = n_base + nf * 8;
                unsigned addr = smem_u32(&Bs[(n0 + bRowOff) * LDB + kk + bColOff]);
                ldmB(addr, bf[nf][0], bf[nf][1]);
            }
#pragma unroll
            for (int mf = 0; mf < 2; mf++)
#pragma unroll
                for (int nf = 0; nf < 4; nf++)
                    mma16816(acc[mf][nf], af[mf], bf[nf]);
        }
        __syncthreads();   // Enc reads done -> reuse R1 as Xl

        float* Xls = reinterpret_cast<float*>(R1);
        int r = lane >> 2, cp = lane & 3;
#pragma unroll
        for (int mf = 0; mf < 2; mf++) {
#pragma unroll
            for (int nf = 0; nf < 4; nf++) {
                int m = m_base + mf * 16 + r;
                int n = n_base + nf * 8 + cp * 2;
                *reinterpret_cast<float2*>(&Xls[m * LDX + n]) =
                    make_float2(acc[mf][nf][0], acc[mf][nf][1]);
                *reinterpret_cast<float2*>(&Xls[(m + 8) * LDX + n]) =
                    make_float2(acc[mf][nf][2], acc[mf][nf][3]);
            }
        }
    }
    __syncthreads();

    // ---- phase 3: combine (4 sequences) -> fp16 states into Bs [128..192) ----
    if (tid < 128) {
        const float* Xls = reinterpret_cast<const float*>(R1);
        int n = tid & 31, bl = tid >> 5;      // local batch 0..3
        float wtr = wTr[n], wti = wTi[n];
        float XR = 0.f, XI = 0.f;
        const float* xR = &Xls[n * LDX];
        const float* xI = &Xls[(n + 32) * LDX];
#pragma unroll 4
        for (int c = 0; c < Cc; c++) {
            int bc = bl * Cc + c;             // local row 0..127
            Bs[bc * LDB + 128 + n] = __float2half(XR);
            Bs[bc * LDB + 160 + n] = __float2half(XI);
            float lr = xR[bc], li = xI[bc];
            float nR = wtr * XR - wti * XI + lr;
            float nI = wtr * XI + wti * XR + li;
            XR = nR; XI = nI;
        }
    }
    __syncthreads();   // Xl reads done -> reuse R1 as A panel

    // ---- phase 4a: inline A panel (Dec + Ks, then Toeplitz) ----
    __half* As = R1;
    {
        int n = tid & 31, w = tid >> 5;
        float ar = P.ar[n], ai = P.ai[n];
        float cr = P.cr[n], ci = P.ci[n];
        float wr = P.wr[n], wi = P.wi[n];
#pragma unroll
        for (int q = 0; q < 16; q++) {
            int sp = w * 16 + q;
            float fs = (float)sp;
            float er = __expf(fs * ar);
            float sn, cs;
            sincosf(fs * ai, &sn, &cs);
            float pr = er * cs, pi = er * sn;           // w^{s'}
            float tr = cr * pr - ci * pi;
            float ti = cr * pi + ci * pr;               // c' w^{s'}
            float dr = tr * wr - ti * wi;
            float di = tr * wi + ti * wr;               // c' w^{s'+1}
            As[sp * LDA2 + 128 + n] = __float2half(2.0f * dr);
            As[sp * LDA2 + 160 + n] = __float2half(-2.0f * di);
            float term = 2.0f * tr;
#pragma unroll
            for (int off = 16; off; off >>= 1)
                term += __shfl_xor_sync(0xffffffffu, term, off);
            if (n == 0) Ksh[sp] = term;
        }
    }
    __syncthreads();
    for (int i = tid; i < 128 * 16; i += 256) {
        int row = i >> 4, ch = i & 15;
        int j0 = ch * 8;
        __half hv[8];
#pragma unroll
        for (int k = 0; k < 8; k++) {
            int j = j0 + k;
            hv[k] = __float2half((row >= j) ? Ksh[row - j] : 0.f);
        }
        *reinterpret_cast<uint4*>(&As[row * LDA2 + j0]) =
            *reinterpret_cast<const uint4*>(hv);
    }
    __syncthreads();

    // ---- phase 4b: main GEMM  Y[128,128] = [Toep|Dec] @ B^T ----
    int wm = wid >> 2, wn2 = wid & 3;    // balanced short/long warps per SMSP
    int m_base = wm * 64, n_base = wn2 * 32;
    unsigned aBase = smem_u32(&As[(m_base + aRowOff) * LDA2 + aColOff]);
    unsigned bBase = smem_u32(&Bs[(n_base + bRowOff) * LDB + bColOff]);

    float acc[4][4][4];
#pragma unroll
    for (int a = 0; a < 4; a++)
#pragma unroll
        for (int bI = 0; bI < 4; bI++)
#pragma unroll
            for (int cI = 0; cI < 4; cI++) acc[a][bI][cI] = 0.f;

    unsigned af[2][4][4];
    unsigned bf[2][4][2];

#define LOAD_AB(buf, ks_)                                                     \
    {                                                                         \
        const int kk_ = (ks_) * 16;                                           \
        _Pragma("unroll")                                                     \
        for (int mf = 0; mf < 4; mf++)                                        \
            ldmA(aBase + (unsigned)((mf * 16 * LDA2 + kk_) * 2),              \
                 af[buf][mf][0], af[buf][mf][1], af[buf][mf][2], af[buf][mf][3]); \
        _Pragma("unroll")                                                     \
        for (int nf = 0; nf < 4; nf++)                                        \
            ldmB(bBase + (unsigned)((nf * 8 * LDB + kk_) * 2),                \
                 bf[buf][nf][0], bf[buf][nf][1]);                             \
    }
#define MMA_STEP(buf)                                                         \
    {                                                                         \
        _Pragma("unroll")                                                     \
        for (int mf = 0; mf < 4; mf++)                                        \
            _Pragma("unroll")                                                 \
            for (int nf = 0; nf < 4; nf++)                                    \
                mma16816(acc[mf][nf], af[buf][mf], bf[buf][nf]);              \
    }

    if (wm == 0) {
        // rows m<64: Toeplitz cols 64..127 are zero -> k-steps {0..3, 8..11}
        LOAD_AB(0, 0)
#pragma unroll
        for (int it = 0; it < 8; it++) {
            int cur = it & 1;
            if (it < 7) {
                int nks = (it + 1 < 4) ? (it + 1) : (it + 5);
                LOAD_AB(cur ^ 1, nks)
            }
            MMA_STEP(cur)
        }
    } else {
        LOAD_AB(0, 0)
#pragma unroll
        for (int it = 0; it < 12; it++) {
            int cur = it & 1;
            if (it < 11) LOAD_AB(cur ^ 1, it + 1)
            MMA_STEP(cur)
        }
    }
#undef LOAD_AB
#undef MMA_STEP

    // ---- phase 5: epilogue -> stage fp16 in R1, coalesced global store ----
    __syncthreads();   // A-panel reads done -> reuse R1 as staging
    __half* ot = R1;   // [128 bc][LDO]
    {
        int r = lane >> 2, cp = lane & 3;
#pragma unroll
        for (int mf = 0; mf < 4; mf++) {
            int m = m_base + mf * 16 + r;
#pragma unroll
            for (int nf = 0; nf < 4; nf++) {
                int n = n_base + nf * 8 + cp * 2;
                ot[n * LDO + m]           = __float2half(acc[mf][nf][0]);
                ot[(n + 1) * LDO + m]     = __float2half(acc[mf][nf][1]);
                ot[n * LDO + m + 8]       = __float2half(acc[mf][nf][2]);
                ot[(n + 1) * LDO + m + 8] = __float2half(acc[mf][nf][3]);
            }
        }
    }
    __syncthreads();
    {
        __half* dst = g_yT16 + ((size_t)h * BC + half * 128) * Tn;
        for (int i = tid; i < 128 * 16; i += 256) {
            int row = i >> 4, ch = i & 15;
            *reinterpret_cast<uint4*>(&dst[row * Tn + ch * 8]) =
                *reinterpret_cast<const uint4*>(&ot[row * LDO + ch * 8]);
        }
    }
}

// =====================================================================
// k_final: transpose yT16 -> (b,l,h), + D*u (skipped when D==0), GELU
// =====================================================================
__global__ void __launch_bounds__(256)
k_final(const float* __restrict__ u, const float* __restrict__ Dp,
        float* __restrict__ out) {
    int ht = blockIdx.x, c = blockIdx.y, b = blockIdx.z;
    __shared__ float ys[128][33];
    int bc = b * Cc + c;

    {
#pragma unroll
        for (int q = 0; q < 2; q++) {
            int idx = threadIdx.x + q * 256;
            int row = idx >> 4;
            int ch = idx & 15;
            const uint4* src = reinterpret_cast<const uint4*>(
                g_yT16 + ((size_t)(ht * 32 + row) * BC + bc) * Tn);
            uint4 v = src[ch];
            const __half* hp = reinterpret_cast<const __half*>(&v);
            int i = ch * 8;
#pragma unroll
            for (int k = 0; k < 8; k++)
                ys[i + k][row] = __half2float(hp[k]);
        }
    }
    __syncthreads();

    float Dv = *Dp;
    int lane = threadIdx.x & 31;
    int r = threadIdx.x >> 5;
    size_t base = ((size_t)b * Ln + (size_t)c * Tn + r) * Hn + ht * 32 + lane;
    if (Dv != 0.0f) {
#pragma unroll
        for (int i0 = 0; i0 < Tn; i0 += 8) {
            int i = i0 + r;
            size_t gidx = base + (size_t)i0 * Hn;
            float v = ys[i][lane] + Dv * u[gidx];
            out[gidx] = gelu_erf(v);
        }
    } else {
#pragma unroll
        for (int i0 = 0; i0 < Tn; i0 += 8) {
            int i = i0 + r;
            size_t gidx = base + (size_t)i0 * Hn;
            out[gidx] = gelu_erf(ys[i][lane]);
        }
    }
}

// =====================================================================
// launch
// =====================================================================
extern "C" void kernel_launch(void* const* d_in, const int* in_sizes, int n_in,
                              void* d_out, int out_size) {
    (void)in_sizes; (void)n_in; (void)out_size;
    const float* u      = (const float*)d_in[0];
    const float* log_dt = (const float*)d_in[1];
    const float* A_real = (const float*)d_in[2];
    const float* A_imag = (const float*)d_in[3];
    const float* C_real = (const float*)d_in[4];
    const float* C_imag = (const float*)d_in[5];
    const float* D      = (const float*)d_in[6];
    float* out = (float*)d_out;

    static bool attr_done = false;
    if (!attr_done) {
        cudaFuncSetAttribute(k_fused, cudaFuncAttributeMaxDynamicSharedMemorySize,
                             SMEM_FUSED);
        attr_done = true;
    }

    k_transpose<<<dim3(Hn / 32, Cc, Bn), 256>>>(u);
    k_fused<<<dim3(Hn, 2), 256, SMEM_FUSED>>>(log_dt, A_real, A_imag, C_real, C_imag);
    k_final<<<dim3(Hn / 32, Cc, Bn), 256>>>(u, D, out);
}

// round 9
// speedup vs baseline: 3.6747x; 1.1582x over previous
#include <cuda_runtime.h>
#include <cuda_fp16.h>
#include <math.h>

// Problem constants
#define Bn 8
#define Ln 4096
#define Hn 1024
#define Nn 32
#define Tn 128            // chunk length
#define Cc 32             // chunks (Tn*Cc == Ln)
#define BC 256            // B*C columns
#define KD 192            // main GEMM K dim: 128 (u) + 64 (states)

// ---- persistent device buffers (no allocs allowed) ----
__device__ __align__(256) __half  g_V[(size_t)Hn * BC * 128];  // per-h u operand [256][128]
__device__ __align__(256) __half  g_yT16[(size_t)Hn * BC * Tn];// per-h output [256][128] fp16

// ---- small helpers ----
static __device__ __forceinline__ unsigned smem_u32(const void* p) {
    unsigned r;
    asm("{ .reg .u64 t; cvta.to.shared.u64 t, %1; cvt.u32.u64 %0, t; }"
        : "=r"(r) : "l"(p));
    return r;
}
static __device__ __forceinline__ void cp16(unsigned dst, const void* src) {
    asm volatile("cp.async.cg.shared.global [%0], [%1], 16;" :: "r"(dst), "l"(src));
}
static __device__ __forceinline__ void cp_commit() {
    asm volatile("cp.async.commit_group;");
}
static __device__ __forceinline__ void cp_wait_all() {
    asm volatile("cp.async.wait_group 0;");
}
static __device__ __forceinline__ void ldmA(unsigned addr, unsigned& r0, unsigned& r1,
                                            unsigned& r2, unsigned& r3) {
    asm volatile("ldmatrix.sync.aligned.m8n8.x4.shared.b16 {%0,%1,%2,%3}, [%4];"
                 : "=r"(r0), "=r"(r1), "=r"(r2), "=r"(r3) : "r"(addr));
}
static __device__ __forceinline__ void ldmB(unsigned addr, unsigned& r0, unsigned& r1) {
    asm volatile("ldmatrix.sync.aligned.m8n8.x2.shared.b16 {%0,%1}, [%2];"
                 : "=r"(r0), "=r"(r1) : "r"(addr));
}
static __device__ __forceinline__ void mma16816(float* d, const unsigned* a,
                                                const unsigned* b) {
    asm volatile(
        "mma.sync.aligned.m16n8k16.row.col.f32.f16.f16.f32 "
        "{%0,%1,%2,%3}, {%4,%5,%6,%7}, {%8,%9}, {%0,%1,%2,%3};"
        : "+f"(d[0]), "+f"(d[1]), "+f"(d[2]), "+f"(d[3])
        : "r"(a[0]), "r"(a[1]), "r"(a[2]), "r"(a[3]), "r"(b[0]), "r"(b[1]));
}

// Fast branch-free erf-GELU (A&S 7.1.26, |eps_erf| < 1.5e-7)
static __device__ __forceinline__ float gelu_erf(float v) {
    float z = fabsf(v) * 0.70710678118654752440f;
    float t = __fdividef(1.0f, fmaf(0.3275911f, z, 1.0f));
    float p = fmaf(1.061405429f, t, -1.453152027f);
    p = fmaf(p, t, 1.421413741f);
    p = fmaf(p, t, -0.284496736f);
    p = fmaf(p, t, 0.254829592f);
    p *= t;
    float e = __expf(-z * z);
    float erfz = fmaf(-p, e, 1.0f);          // erf(|v|/sqrt2)
    float erfv = copysignf(erfz, v);
    return 0.5f * v * (1.0f + erfv);
}

// Per-mode recurrence params: w = exp(dt*A), c' = C*(w-1)/A
struct ModeParams {
    float ar[32], ai[32];       // log|w|, arg w
    float wr[32], wi[32];       // w
    float cr[32], ci[32];       // c'
};
static __device__ __forceinline__ void compute_params(
    ModeParams& P, int h, int n,
    const float* __restrict__ log_dt, const float* __restrict__ A_real,
    const float* __restrict__ A_imag, const float* __restrict__ C_real,
    const float* __restrict__ C_imag) {
    int idx = h * Nn + n;
    float dt = expf(log_dt[h]);
    float Ar = -expf(A_real[idx]);
    float Ai = A_imag[idx];
    float ar = Ar * dt, ai = Ai * dt;
    float er = expf(ar);
    float sn, cs;
    sincosf(ai, &sn, &cs);
    float wr = er * cs, wi = er * sn;
    float den = Ar * Ar + Ai * Ai;
    float e1r = wr - 1.0f, e1i = wi;
    float qr = (e1r * Ar + e1i * Ai) / den;
    float qi = (e1i * Ar - e1r * Ai) / den;
    float Cr = C_real[idx], Ci = C_imag[idx];
    P.ar[n] = ar; P.ai[n] = ai;
    P.wr[n] = wr; P.wi[n] = wi;
    P.cr[n] = Cr * qr - Ci * qi;
    P.ci[n] = Cr * qi + Ci * qr;
}

// =====================================================================
// k_transpose: u (b,l,h) fp32 -> g_V[h][bc][0..128) fp16
// =====================================================================
__global__ void __launch_bounds__(256)
k_transpose(const float* __restrict__ u) {
    int ht = blockIdx.x, c = blockIdx.y, b = blockIdx.z;
    __shared__ __half ts[32][136];
    int lane = threadIdx.x & 31;
    int r = threadIdx.x >> 5;

    const float* up = u + ((size_t)b * Ln + (size_t)c * Tn) * Hn + ht * 32;
#pragma unroll
    for (int j0 = 0; j0 < Tn; j0 += 8) {
        int j = j0 + r;
        ts[lane][j] = __float2half(up[(size_t)j * Hn + lane]);
    }
    __syncthreads();

    int row = threadIdx.x >> 3;
    int ch = threadIdx.x & 7;
    int bc = b * Cc + c;
    __half* dst = g_V + ((size_t)(ht * 32 + row) * BC + bc) * 128;
    reinterpret_cast<uint4*>(dst)[ch] =
        *reinterpret_cast<const uint4*>(&ts[row][ch * 8]);
    reinterpret_cast<uint4*>(dst)[ch + 8] =
        *reinterpret_cast<const uint4*>(&ts[row][(ch + 8) * 8]);
}

// =====================================================================
// k_fused: one block per (h, batch-half). Half = 4 sequences = 128 bc.
//   phase 1: cp.async u-tile [128][128] -> Bs cols 0..127
//   phase 2: inline Enc (chained w^s); encode GEMM -> Xl[64][128]
//   phase 3: combine (4 seqs) -> fp16 states into Bs cols 128..191
//   phase 4: inline A panel (chained c'w^s); main GEMM 128x128x192
//   phase 5: epilogue -> g_yT16[h][half*128+bc][m] fp16 coalesced
// 102.4KB smem -> 2 CTAs/SM.
// =====================================================================
#define LDB  200     // Bs row stride (halves)
#define LDA1 136     // Enc row stride
#define LDX  130     // Xl fp32 row stride
#define LDA2 200     // main A row stride
#define LDO  136     // epilogue staging stride
#define R1_OFF (128 * LDB)                    // halves
#define SMEM_FUSED ((128 * LDB) * 2 + 51200)  // bytes = 102400

__global__ void __launch_bounds__(256, 2)
k_fused(const float* __restrict__ log_dt, const float* __restrict__ A_real,
        const float* __restrict__ A_imag, const float* __restrict__ C_real,
        const float* __restrict__ C_imag) {
    int h = blockIdx.x;
    int half = blockIdx.y;
    int tid = threadIdx.x;
    extern __shared__ __half sm[];
    __half* Bs = sm;                 // [128][LDB]
    __half* R1 = sm + R1_OFF;        // 51200B scratch: Enc / Xl / A / epilogue
    __shared__ ModeParams P;
    __shared__ float wTr[32], wTi[32], Ksh[Tn];

    // ---- phase 1: async u-tile (128 bc rows of this half) ----
    {
        const __half* vb = g_V + ((size_t)h * BC + half * 128) * 128;
        unsigned bsm = smem_u32(Bs);
        for (int i = tid; i < 128 * 16; i += 256) {
            int row = i >> 4, ch = i & 15;
            cp16(bsm + (unsigned)((row * LDB + ch * 8) * 2),
                 vb + (size_t)row * 128 + ch * 8);
        }
        cp_commit();
    }
    if (tid < 32) {
        compute_params(P, h, tid, log_dt, A_real, A_imag, C_real, C_imag);
        float erT = __expf(128.f * P.ar[tid]);
        float snT, csT;
        sincosf(128.f * P.ai[tid], &snT, &csT);
        wTr[tid] = erT * csT; wTi[tid] = erT * snT;
    }
    __syncthreads();

    int n = tid & 31, w16 = tid >> 5;
    float ar = P.ar[n], ai = P.ai[n];
    float wr = P.wr[n], wi = P.wi[n];
    // base power w^{s0}, s0 = w16*16  (one transcendental set per thread)
    float s0 = (float)(w16 * 16);
    float pBr, pBi;
    {
        float er = __expf(s0 * ar);
        float sn, cs;
        sincosf(s0 * ai, &sn, &cs);
        pBr = er * cs; pBi = er * sn;
    }

    // ---- phase 2a: inline Enc into R1 (chained) ----
    __half* EncS = R1;
    {
        float pr = pBr, pi = pBi;
#pragma unroll
        for (int q = 0; q < 16; q++) {
            int s = w16 * 16 + q;
            EncS[n * LDA1 + (127 - s)]        = __float2half(pr);
            EncS[(n + 32) * LDA1 + (127 - s)] = __float2half(pi);
            float nr = pr * wr - pi * wi;
            float ni = pr * wi + pi * wr;
            pr = nr; pi = ni;
        }
    }
    cp_wait_all();
    __syncthreads();

    int wid = tid >> 5, lane = tid & 31;
    int la = lane & 15;
    int aRowOff = (lane < 16) ? lane : (lane - 16);
    int aColOff = (lane < 16) ? 0 : 8;
    int bRowOff = la & 7;
    int bColOff = (la >> 3) * 8;

    // ---- phase 2b: encode GEMM  Xl[64,128] = Enc @ B_u^T ----
    {
        int wm = wid & 1, wn = wid >> 1;
        int m_base = wm * 32, n_base = wn * 32;

        float acc[2][4][4];
#pragma unroll
        for (int a = 0; a < 2; a++)
#pragma unroll
            for (int bI = 0; bI < 4; bI++)
#pragma unroll
                for (int cI = 0; cI < 4; cI++) acc[a][bI][cI] = 0.f;

#pragma unroll
        for (int kk = 0; kk < 128; kk += 16) {
            unsigned af[2][4];
#pragma unroll
            for (int mf = 0; mf < 2; mf++) {
                int m0 = m_base + mf * 16;
                unsigned addr = smem_u32(&EncS[(m0 + aRowOff) * LDA1 + kk + aColOff]);
                ldmA(addr, af[mf][0], af[mf][1], af[mf][2], af[mf][3]);
            }
            unsigned bf[4][2];
#pragma unroll
            for (int nf = 0; nf < 4; nf++) {
                int n0 = n_base + nf * 8;
                unsigned addr = smem_u32(&Bs[(n0 + bRowOff) * LDB + kk + bColOff]);
                ldmB(addr, bf[nf][0], bf[nf][1]);
            }
#pragma unroll
            for (int mf = 0; mf < 2; mf++)
#pragma unroll
                for (int nf = 0; nf < 4; nf++)
                    mma16816(acc[mf][nf], af[mf], bf[nf]);
        }
        __syncthreads();   // Enc reads done -> reuse R1 as Xl

        float* Xls = reinterpret_cast<float*>(R1);
        int r = lane >> 2, cp = lane & 3;
#pragma unroll
        for (int mf = 0; mf < 2; mf++) {
#pragma unroll
            for (int nf = 0; nf < 4; nf++) {
                int m = m_base + mf * 16 + r;
                int nn = n_base + nf * 8 + cp * 2;
                *reinterpret_cast<float2*>(&Xls[m * LDX + nn]) =
                    make_float2(acc[mf][nf][0], acc[mf][nf][1]);
                *reinterpret_cast<float2*>(&Xls[(m + 8) * LDX + nn]) =
                    make_float2(acc[mf][nf][2], acc[mf][nf][3]);
            }
        }
    }
    __syncthreads();

    // ---- phase 3: combine (4 sequences) -> fp16 states into Bs [128..192) ----
    if (tid < 128) {
        const float* Xls = reinterpret_cast<const float*>(R1);
        int bl = tid >> 5;      // local batch 0..3
        float wtr = wTr[n], wti = wTi[n];
        float XR = 0.f, XI = 0.f;
        const float* xR = &Xls[n * LDX];
        const float* xI = &Xls[(n + 32) * LDX];
#pragma unroll 4
        for (int c = 0; c < Cc; c++) {
            int bc = bl * Cc + c;             // local row 0..127
            Bs[bc * LDB + 128 + n] = __float2half(XR);
            Bs[bc * LDB + 160 + n] = __float2half(XI);
            float lr = xR[bc], li = xI[bc];
            float nR = wtr * XR - wti * XI + lr;
            float nI = wtr * XI + wti * XR + li;
            XR = nR; XI = nI;
        }
    }
    __syncthreads();   // Xl reads done -> reuse R1 as A panel

    // ---- phase 4a: inline A panel (Dec + Ks chained, then Toeplitz) ----
    __half* As = R1;
    {
        float cr = P.cr[n], ci = P.ci[n];
        // t = c' * w^{s0}
        float tr = cr * pBr - ci * pBi;
        float ti = cr * pBi + ci * pBr;
#pragma unroll
        for (int q = 0; q < 16; q++) {
            int sp = w16 * 16 + q;
            float dr = tr * wr - ti * wi;
            float di = tr * wi + ti * wr;               // c' w^{sp+1}
            As[sp * LDA2 + 128 + n] = __float2half(2.0f * dr);
            As[sp * LDA2 + 160 + n] = __float2half(-2.0f * di);
            float term = 2.0f * tr;
#pragma unroll
            for (int off = 16; off; off >>= 1)
                term += __shfl_xor_sync(0xffffffffu, term, off);
            if (n == 0) Ksh[sp] = term;
            tr = dr; ti = di;                           // advance chain
        }
    }
    __syncthreads();
    for (int i = tid; i < 128 * 16; i += 256) {
        int row = i >> 4, ch = i & 15;
        int j0 = ch * 8;
        __half hv[8];
#pragma unroll
        for (int k = 0; k < 8; k++) {
            int j = j0 + k;
            hv[k] = __float2half((row >= j) ? Ksh[row - j] : 0.f);
        }
        *reinterpret_cast<uint4*>(&As[row * LDA2 + j0]) =
            *reinterpret_cast<const uint4*>(hv);
    }
    __syncthreads();

    // ---- phase 4b: main GEMM  Y[128,128] = [Toep|Dec] @ B^T ----
    int wm = wid >> 2, wn2 = wid & 3;    // balanced short/long warps per SMSP
    int m_base = wm * 64, n_base = wn2 * 32;
    unsigned aBase = smem_u32(&As[(m_base + aRowOff) * LDA2 + aColOff]);
    unsigned bBase = smem_u32(&Bs[(n_base + bRowOff) * LDB + bColOff]);

    float acc[4][4][4];
#pragma unroll
    for (int a = 0; a < 4; a++)
#pragma unroll
        for (int bI = 0; bI < 4; bI++)
#pragma unroll
            for (int cI = 0; cI < 4; cI++) acc[a][bI][cI] = 0.f;

    unsigned af[2][4][4];
    unsigned bf[2][4][2];

#define LOAD_AB(buf, ks_)                                                     \
    {                                                                         \
        const int kk_ = (ks_) * 16;                                           \
        _Pragma("unroll")                                                     \
        for (int mf = 0; mf < 4; mf++)                                        \
            ldmA(aBase + (unsigned)((mf * 16 * LDA2 + kk_) * 2),              \
                 af[buf][mf][0], af[buf][mf][1], af[buf][mf][2], af[buf][mf][3]); \
        _Pragma("unroll")                                                     \
        for (int nf = 0; nf < 4; nf++)                                        \
            ldmB(bBase + (unsigned)((nf * 8 * LDB + kk_) * 2),                \
                 bf[buf][nf][0], bf[buf][nf][1]);                             \
    }
#define MMA_STEP(buf)                                                         \
    {                                                                         \
        _Pragma("unroll")                                                     \
        for (int mf = 0; mf < 4; mf++)                                        \
            _Pragma("unroll")                                                 \
            for (int nf = 0; nf < 4; nf++)                                    \
                mma16816(acc[mf][nf], af[buf][mf], bf[buf][nf]);              \
    }

    if (wm == 0) {
        // rows m<64: Toeplitz cols 64..127 are zero -> k-steps {0..3, 8..11}
        LOAD_AB(0, 0)
#pragma unroll
        for (int it = 0; it < 8; it++) {
            int cur = it & 1;
            if (it < 7) {
                int nks = (it + 1 < 4) ? (it + 1) : (it + 5);
                LOAD_AB(cur ^ 1, nks)
            }
            MMA_STEP(cur)
        }
    } else {
        LOAD_AB(0, 0)
#pragma unroll
        for (int it = 0; it < 12; it++) {
            int cur = it & 1;
            if (it < 11) LOAD_AB(cur ^ 1, it + 1)
            MMA_STEP(cur)
        }
    }
#undef LOAD_AB
#undef MMA_STEP

    // ---- phase 5: epilogue -> stage fp16 in R1, coalesced global store ----
    __syncthreads();   // A-panel reads done -> reuse R1 as staging
    __half* ot = R1;   // [128 bc][LDO]
    {
        int r = lane >> 2, cp = lane & 3;
#pragma unroll
        for (int mf = 0; mf < 4; mf++) {
            int m = m_base + mf * 16 + r;
#pragma unroll
            for (int nf = 0; nf < 4; nf++) {
                int nn = n_base + nf * 8 + cp * 2;
                ot[nn * LDO + m]           = __float2half(acc[mf][nf][0]);
                ot[(nn + 1) * LDO + m]     = __float2half(acc[mf][nf][1]);
                ot[nn * LDO + m + 8]       = __float2half(acc[mf][nf][2]);
                ot[(nn + 1) * LDO + m + 8] = __float2half(acc[mf][nf][3]);
            }
        }
    }
    __syncthreads();
    {
        __half* dst = g_yT16 + ((size_t)h * BC + half * 128) * Tn;
        for (int i = tid; i < 128 * 16; i += 256) {
            int row = i >> 4, ch = i & 15;
            *reinterpret_cast<uint4*>(&dst[row * Tn + ch * 8]) =
                *reinterpret_cast<const uint4*>(&ot[row * LDO + ch * 8]);
        }
    }
}

// =====================================================================
// k_final: transpose yT16 -> (b,l,h), + D*u (skipped when D==0), GELU
// =====================================================================
__global__ void __launch_bounds__(256)
k_final(const float* __restrict__ u, const float* __restrict__ Dp,
        float* __restrict__ out) {
    int ht = blockIdx.x, c = blockIdx.y, b = blockIdx.z;
    __shared__ float ys[128][33];
    int bc = b * Cc + c;

    {
#pragma unroll
        for (int q = 0; q < 2; q++) {
            int idx = threadIdx.x + q * 256;
            int row = idx >> 4;
            int ch = idx & 15;
            const uint4* src = reinterpret_cast<const uint4*>(
                g_yT16 + ((size_t)(ht * 32 + row) * BC + bc) * Tn);
            uint4 v = src[ch];
            const __half* hp = reinterpret_cast<const __half*>(&v);
            int i = ch * 8;
#pragma unroll
            for (int k = 0; k < 8; k++)
                ys[i + k][row] = __half2float(hp[k]);
        }
    }
    __syncthreads();

    float Dv = *Dp;
    int lane = threadIdx.x & 31;
    int r = threadIdx.x >> 5;
    size_t base = ((size_t)b * Ln + (size_t)c * Tn + r) * Hn + ht * 32 + lane;
    if (Dv != 0.0f) {
#pragma unroll
        for (int i0 = 0; i0 < Tn; i0 += 8) {
            int i = i0 + r;
            size_t gidx = base + (size_t)i0 * Hn;
            float v = ys[i][lane] + Dv * u[gidx];
            out[gidx] = gelu_erf(v);
        }
    } else {
#pragma unroll
        for (int i0 = 0; i0 < Tn; i0 += 8) {
            int i = i0 + r;
            size_t gidx = base + (size_t)i0 * Hn;
            out[gidx] = gelu_erf(ys[i][lane]);
        }
    }
}

// =====================================================================
// launch
// =====================================================================
extern "C" void kernel_launch(void* const* d_in, const int* in_sizes, int n_in,
                              void* d_out, int out_size) {
    (void)in_sizes; (void)n_in; (void)out_size;
    const float* u      = (const float*)d_in[0];
    const float* log_dt = (const float*)d_in[1];
    const float* A_real = (const float*)d_in[2];
    const float* A_imag = (const float*)d_in[3];
    const float* C_real = (const float*)d_in[4];
    const float* C_imag = (const float*)d_in[5];
    const float* D      = (const float*)d_in[6];
    float* out = (float*)d_out;

    static bool attr_done = false;
    if (!attr_done) {
        cudaFuncSetAttribute(k_fused, cudaFuncAttributeMaxDynamicSharedMemorySize,
                             SMEM_FUSED);
        attr_done = true;
    }

    k_transpose<<<dim3(Hn / 32, Cc, Bn), 256>>>(u);
    k_fused<<<dim3(Hn, 2), 256, SMEM_FUSED>>>(log_dt, A_real, A_imag, C_real, C_imag);
    k_final<<<dim3(Hn / 32, Cc, Bn), 256>>>(u, D, out);
}

// round 11
// speedup vs baseline: 3.7072x; 1.0088x over previous
#include <cuda_runtime.h>
#include <cuda_fp16.h>
#include <math.h>

// Problem constants
#define Bn 8
#define Ln 4096
#define Hn 1024
#define Nn 32
#define Tn 128            // chunk length
#define Cc 32             // chunks (Tn*Cc == Ln)
#define BC 256            // B*C columns
#define KD 192            // main GEMM K dim: 128 (u) + 64 (states)

// ---- persistent device buffers (no allocs allowed) ----
__device__ __align__(256) __half  g_V[(size_t)Hn * BC * 128];  // per-h u operand [256][128]
__device__ __align__(256) __half  g_yT16[(size_t)Hn * BC * Tn];// per-h output [256][128] fp16

// ---- small helpers ----
static __device__ __forceinline__ unsigned smem_u32(const void* p) {
    unsigned r;
    asm("{ .reg .u64 t; cvta.to.shared.u64 t, %1; cvt.u32.u64 %0, t; }"
        : "=r"(r) : "l"(p));
    return r;
}
static __device__ __forceinline__ void cp16(unsigned dst, const void* src) {
    asm volatile("cp.async.cg.shared.global [%0], [%1], 16;" :: "r"(dst), "l"(src));
}
static __device__ __forceinline__ void cp_commit() {
    asm volatile("cp.async.commit_group;");
}
static __device__ __forceinline__ void cp_wait_all() {
    asm volatile("cp.async.wait_group 0;");
}
static __device__ __forceinline__ void ldmA(unsigned addr, unsigned& r0, unsigned& r1,
                                            unsigned& r2, unsigned& r3) {
    asm volatile("ldmatrix.sync.aligned.m8n8.x4.shared.b16 {%0,%1,%2,%3}, [%4];"
                 : "=r"(r0), "=r"(r1), "=r"(r2), "=r"(r3) : "r"(addr));
}
static __device__ __forceinline__ void ldmB(unsigned addr, unsigned& r0, unsigned& r1) {
    asm volatile("ldmatrix.sync.aligned.m8n8.x2.shared.b16 {%0,%1}, [%2];"
                 : "=r"(r0), "=r"(r1) : "r"(addr));
}
static __device__ __forceinline__ void mma16816(float* d, const unsigned* a,
                                                const unsigned* b) {
    asm volatile(
        "mma.sync.aligned.m16n8k16.row.col.f32.f16.f16.f32 "
        "{%0,%1,%2,%3}, {%4,%5,%6,%7}, {%8,%9}, {%0,%1,%2,%3};"
        : "+f"(d[0]), "+f"(d[1]), "+f"(d[2]), "+f"(d[3])
        : "r"(a[0]), "r"(a[1]), "r"(a[2]), "r"(a[3]), "r"(b[0]), "r"(b[1]));
}

// Fast branch-free erf-GELU (A&S 7.1.26, |eps_erf| < 1.5e-7)
static __device__ __forceinline__ float gelu_erf(float v) {
    float z = fabsf(v) * 0.70710678118654752440f;
    float t = __fdividef(1.0f, fmaf(0.3275911f, z, 1.0f));
    float p = fmaf(1.061405429f, t, -1.453152027f);
    p = fmaf(p, t, 1.421413741f);
    p = fmaf(p, t, -0.284496736f);
    p = fmaf(p, t, 0.254829592f);
    p *= t;
    float e = __expf(-z * z);
    float erfz = fmaf(-p, e, 1.0f);          // erf(|v|/sqrt2)
    float erfv = copysignf(erfz, v);
    return 0.5f * v * (1.0f + erfv);
}

// Per-mode recurrence params: w = exp(dt*A), c' = C*(w-1)/A
struct ModeParams {
    float ar[32], ai[32];       // log|w|, arg w
    float wr[32], wi[32];       // w
    float cr[32], ci[32];       // c'
};
static __device__ __forceinline__ void compute_params(
    ModeParams& P, int h, int n,
    const float* __restrict__ log_dt, const float* __restrict__ A_real,
    const float* __restrict__ A_imag, const float* __restrict__ C_real,
    const float* __restrict__ C_imag) {
    int idx = h * Nn + n;
    float dt = expf(log_dt[h]);
    float Ar = -expf(A_real[idx]);
    float Ai = A_imag[idx];
    float ar = Ar * dt, ai = Ai * dt;
    float er = expf(ar);
    float sn, cs;
    sincosf(ai, &sn, &cs);
    float wr = er * cs, wi = er * sn;
    float den = Ar * Ar + Ai * Ai;
    float e1r = wr - 1.0f, e1i = wi;
    float qr = (e1r * Ar + e1i * Ai) / den;
    float qi = (e1i * Ar - e1r * Ai) / den;
    float Cr = C_real[idx], Ci = C_imag[idx];
    P.ar[n] = ar; P.ai[n] = ai;
    P.wr[n] = wr; P.wi[n] = wi;
    P.cr[n] = Cr * qr - Ci * qi;
    P.ci[n] = Cr * qi + Ci * qr;
}

// =====================================================================
// k_transpose: u (b,l,h) fp32 -> g_V[h][bc][0..128) fp16  (h-tile offset)
// =====================================================================
__global__ void __launch_bounds__(256)
k_transpose(const float* __restrict__ u, int ht0) {
    int ht = blockIdx.x + ht0, c = blockIdx.y, b = blockIdx.z;
    __shared__ __half ts[32][136];
    int lane = threadIdx.x & 31;
    int r = threadIdx.x >> 5;

    const float* up = u + ((size_t)b * Ln + (size_t)c * Tn) * Hn + ht * 32;
#pragma unroll
    for (int j0 = 0; j0 < Tn; j0 += 8) {
        int j = j0 + r;
        ts[lane][j] = __float2half(up[(size_t)j * Hn + lane]);
    }
    __syncthreads();

    int row = threadIdx.x >> 3;
    int ch = threadIdx.x & 7;
    int bc = b * Cc + c;
    __half* dst = g_V + ((size_t)(ht * 32 + row) * BC + bc) * 128;
    reinterpret_cast<uint4*>(dst)[ch] =
        *reinterpret_cast<const uint4*>(&ts[row][ch * 8]);
    reinterpret_cast<uint4*>(dst)[ch + 8] =
        *reinterpret_cast<const uint4*>(&ts[row][(ch + 8) * 8]);
}

// =====================================================================
// k_fused: one block per (h, batch-half). Half = 4 sequences = 128 bc.
// (identical to R9 body; h offset arg)
// =====================================================================
#define LDB  200     // Bs row stride (halves)
#define LDA1 136     // Enc row stride
#define LDX  130     // Xl fp32 row stride
#define LDA2 200     // main A row stride
#define LDO  136     // epilogue staging stride
#define R1_OFF (128 * LDB)                    // halves
#define SMEM_FUSED ((128 * LDB) * 2 + 51200)  // bytes = 102400

__global__ void __launch_bounds__(256, 2)
k_fused(const float* __restrict__ log_dt, const float* __restrict__ A_real,
        const float* __restrict__ A_imag, const float* __restrict__ C_real,
        const float* __restrict__ C_imag, int h0) {
    int h = blockIdx.x + h0;
    int half = blockIdx.y;
    int tid = threadIdx.x;
    extern __shared__ __half sm[];
    __half* Bs = sm;                 // [128][LDB]
    __half* R1 = sm + R1_OFF;        // 51200B scratch: Enc / Xl / A / epilogue
    __shared__ ModeParams P;
    __shared__ float wTr[32], wTi[32], Ksh[Tn];

    // ---- phase 1: async u-tile (128 bc rows of this half) ----
    {
        const __half* vb = g_V + ((size_t)h * BC + half * 128) * 128;
        unsigned bsm = smem_u32(Bs);
        for (int i = tid; i < 128 * 16; i += 256) {
            int row = i >> 4, ch = i & 15;
            cp16(bsm + (unsigned)((row * LDB + ch * 8) * 2),
                 vb + (size_t)row * 128 + ch * 8);
        }
        cp_commit();
    }
    if (tid < 32) {
        compute_params(P, h, tid, log_dt, A_real, A_imag, C_real, C_imag);
        float erT = __expf(128.f * P.ar[tid]);
        float snT, csT;
        sincosf(128.f * P.ai[tid], &snT, &csT);
        wTr[tid] = erT * csT; wTi[tid] = erT * snT;
    }
    __syncthreads();

    int n = tid & 31, w16 = tid >> 5;
    float ar = P.ar[n], ai = P.ai[n];
    float wr = P.wr[n], wi = P.wi[n];
    // base power w^{s0}, s0 = w16*16  (one transcendental set per thread)
    float s0 = (float)(w16 * 16);
    float pBr, pBi;
    {
        float er = __expf(s0 * ar);
        float sn, cs;
        sincosf(s0 * ai, &sn, &cs);
        pBr = er * cs; pBi = er * sn;
    }

    // ---- phase 2a: inline Enc into R1 (chained) ----
    __half* EncS = R1;
    {
        float pr = pBr, pi = pBi;
#pragma unroll
        for (int q = 0; q < 16; q++) {
            int s = w16 * 16 + q;
            EncS[n * LDA1 + (127 - s)]        = __float2half(pr);
            EncS[(n + 32) * LDA1 + (127 - s)] = __float2half(pi);
            float nr = pr * wr - pi * wi;
            float ni = pr * wi + pi * wr;
            pr = nr; pi = ni;
        }
    }
    cp_wait_all();
    __syncthreads();

    int wid = tid >> 5, lane = tid & 31;
    int la = lane & 15;
    int aRowOff = (lane < 16) ? lane : (lane - 16);
    int aColOff = (lane < 16) ? 0 : 8;
    int bRowOff = la & 7;
    int bColOff = (la >> 3) * 8;

    // ---- phase 2b: encode GEMM  Xl[64,128] = Enc @ B_u^T ----
    {
        int wm = wid & 1, wn = wid >> 1;
        int m_base = wm * 32, n_base = wn * 32;

        float acc[2][4][4];
#pragma unroll
        for (int a = 0; a < 2; a++)
#pragma unroll
            for (int bI = 0; bI < 4; bI++)
#pragma unroll
                for (int cI = 0; cI < 4; cI++) acc[a][bI][cI] = 0.f;

#pragma unroll
        for (int kk = 0; kk < 128; kk += 16) {
            unsigned af[2][4];
#pragma unroll
            for (int mf = 0; mf < 2; mf++) {
                int m0 = m_base + mf * 16;
                unsigned addr = smem_u32(&EncS[(m0 + aRowOff) * LDA1 + kk + aColOff]);
                ldmA(addr, af[mf][0], af[mf][1], af[mf][2], af[mf][3]);
            }
            unsigned bf[4][2];
#pragma unroll
            for (int nf = 0; nf < 4; nf++) {
                int n0 = n_base + nf * 8;
                unsigned addr = smem_u32(&Bs[(n0 + bRowOff) * LDB + kk + bColOff]);
                ldmB(addr, bf[nf][0], bf[nf][1]);
            }
#pragma unroll
            for (int mf = 0; mf < 2; mf++)
#pragma unroll
                for (int nf = 0; nf < 4; nf++)
                    mma16816(acc[mf][nf], af[mf], bf[nf]);
        }
        __syncthreads();   // Enc reads done -> reuse R1 as Xl

        float* Xls = reinterpret_cast<float*>(R1);
        int r = lane >> 2, cp = lane & 3;
#pragma unroll
        for (int mf = 0; mf < 2; mf++) {
#pragma unroll
            for (int nf = 0; nf < 4; nf++) {
                int m = m_base + mf * 16 + r;
                int nn = n_base + nf * 8 + cp * 2;
                *reinterpret_cast<float2*>(&Xls[m * LDX + nn]) =
                    make_float2(acc[mf][nf][0], acc[mf][nf][1]);
                *reinterpret_cast<float2*>(&Xls[(m + 8) * LDX + nn]) =
                    make_float2(acc[mf][nf][2], acc[mf][nf][3]);
            }
        }
    }
    __syncthreads();

    // ---- phase 3: combine (4 sequences) -> fp16 states into Bs [128..192) ----
    if (tid < 128) {
        const float* Xls = reinterpret_cast<const float*>(R1);
        int bl = tid >> 5;      // local batch 0..3
        float wtr = wTr[n], wti = wTi[n];
        float XR = 0.f, XI = 0.f;
        const float* xR = &Xls[n * LDX];
        const float* xI = &Xls[(n + 32) * LDX];
#pragma unroll 4
        for (int c = 0; c < Cc; c++) {
            int bc = bl * Cc + c;             // local row 0..127
            Bs[bc * LDB + 128 + n] = __float2half(XR);
            Bs[bc * LDB + 160 + n] = __float2half(XI);
            float lr = xR[bc], li = xI[bc];
            float nR = wtr * XR - wti * XI + lr;
            float nI = wtr * XI + wti * XR + li;
            XR = nR; XI = nI;
        }
    }
    __syncthreads();   // Xl reads done -> reuse R1 as A panel

    // ---- phase 4a: inline A panel (Dec + Ks chained, then Toeplitz) ----
    __half* As = R1;
    {
        float cr = P.cr[n], ci = P.ci[n];
        // t = c' * w^{s0}
        float tr = cr * pBr - ci * pBi;
        float ti = cr * pBi + ci * pBr;
#pragma unroll
        for (int q = 0; q < 16; q++) {
            int sp = w16 * 16 + q;
            float dr = tr * wr - ti * wi;
            float di = tr * wi + ti * wr;               // c' w^{sp+1}
            As[sp * LDA2 + 128 + n] = __float2half(2.0f * dr);
            As[sp * LDA2 + 160 + n] = __float2half(-2.0f * di);
            float term = 2.0f * tr;
#pragma unroll
            for (int off = 16; off; off >>= 1)
                term += __shfl_xor_sync(0xffffffffu, term, off);
            if (n == 0) Ksh[sp] = term;
            tr = dr; ti = di;                           // advance chain
        }
    }
    __syncthreads();
    for (int i = tid; i < 128 * 16; i += 256) {
        int row = i >> 4, ch = i & 15;
        int j0 = ch * 8;
        __half hv[8];
#pragma unroll
        for (int k = 0; k < 8; k++) {
            int j = j0 + k;
            hv[k] = __float2half((row >= j) ? Ksh[row - j] : 0.f);
        }
        *reinterpret_cast<uint4*>(&As[row * LDA2 + j0]) =
            *reinterpret_cast<const uint4*>(hv);
    }
    __syncthreads();

    // ---- phase 4b: main GEMM  Y[128,128] = [Toep|Dec] @ B^T ----
    int wm = wid >> 2, wn2 = wid & 3;    // balanced short/long warps per SMSP
    int m_base = wm * 64, n_base = wn2 * 32;
    unsigned aBase = smem_u32(&As[(m_base + aRowOff) * LDA2 + aColOff]);
    unsigned bBase = smem_u32(&Bs[(n_base + bRowOff) * LDB + bColOff]);

    float acc[4][4][4];
#pragma unroll
    for (int a = 0; a < 4; a++)
#pragma unroll
        for (int bI = 0; bI < 4; bI++)
#pragma unroll
            for (int cI = 0; cI < 4; cI++) acc[a][bI][cI] = 0.f;

    unsigned af[2][4][4];
    unsigned bf[2][4][2];

#define LOAD_AB(buf, ks_)                                                     \
    {                                                                         \
        const int kk_ = (ks_) * 16;                                           \
        _Pragma("unroll")                                                     \
        for (int mf = 0; mf < 4; mf++)                                        \
            ldmA(aBase + (unsigned)((mf * 16 * LDA2 + kk_) * 2),              \
                 af[buf][mf][0], af[buf][mf][1], af[buf][mf][2], af[buf][mf][3]); \
        _Pragma("unroll")                                                     \
        for (int nf = 0; nf < 4; nf++)                                        \
            ldmB(bBase + (unsigned)((nf * 8 * LDB + kk_) * 2),                \
                 bf[buf][nf][0], bf[buf][nf][1]);                             \
    }
#define MMA_STEP(buf)                                                         \
    {                                                                         \
        _Pragma("unroll")                                                     \
        for (int mf = 0; mf < 4; mf++)                                        \
            _Pragma("unroll")                                                 \
            for (int nf = 0; nf < 4; nf++)                                    \
                mma16816(acc[mf][nf], af[buf][mf], bf[buf][nf]);              \
    }

    if (wm == 0) {
        // rows m<64: Toeplitz cols 64..127 are zero -> k-steps {0..3, 8..11}
        LOAD_AB(0, 0)
#pragma unroll
        for (int it = 0; it < 8; it++) {
            int cur = it & 1;
            if (it < 7) {
                int nks = (it + 1 < 4) ? (it + 1) : (it + 5);
                LOAD_AB(cur ^ 1, nks)
            }
            MMA_STEP(cur)
        }
    } else {
        LOAD_AB(0, 0)
#pragma unroll
        for (int it = 0; it < 12; it++) {
            int cur = it & 1;
            if (it < 11) LOAD_AB(cur ^ 1, it + 1)
            MMA_STEP(cur)
        }
    }
#undef LOAD_AB
#undef MMA_STEP

    // ---- phase 5: epilogue -> stage fp16 in R1, coalesced global store ----
    __syncthreads();   // A-panel reads done -> reuse R1 as staging
    __half* ot = R1;   // [128 bc][LDO]
    {
        int r = lane >> 2, cp = lane & 3;
#pragma unroll
        for (int mf = 0; mf < 4; mf++) {
            int m = m_base + mf * 16 + r;
#pragma unroll
            for (int nf = 0; nf < 4; nf++) {
                int nn = n_base + nf * 8 + cp * 2;
                ot[nn * LDO + m]           = __float2half(acc[mf][nf][0]);
                ot[(nn + 1) * LDO + m]     = __float2half(acc[mf][nf][1]);
                ot[nn * LDO + m + 8]       = __float2half(acc[mf][nf][2]);
                ot[(nn + 1) * LDO + m + 8] = __float2half(acc[mf][nf][3]);
            }
        }
    }
    __syncthreads();
    {
        __half* dst = g_yT16 + ((size_t)h * BC + half * 128) * Tn;
        for (int i = tid; i < 128 * 16; i += 256) {
            int row = i >> 4, ch = i & 15;
            *reinterpret_cast<uint4*>(&dst[row * Tn + ch * 8]) =
                *reinterpret_cast<const uint4*>(&ot[row * LDO + ch * 8]);
        }
    }
}

// =====================================================================
// k_final: transpose yT16 -> (b,l,h), + D*u (skipped when D==0), GELU
// =====================================================================
__global__ void __launch_bounds__(256)
k_final(const float* __restrict__ u, const float* __restrict__ Dp,
        float* __restrict__ out, int ht0) {
    int ht = blockIdx.x + ht0, c = blockIdx.y, b = blockIdx.z;
    __shared__ float ys[128][33];
    int bc = b * Cc + c;

    {
#pragma unroll
        for (int q = 0; q < 2; q++) {
            int idx = threadIdx.x + q * 256;
            int row = idx >> 4;
            int ch = idx & 15;
            const uint4* src = reinterpret_cast<const uint4*>(
                g_yT16 + ((size_t)(ht * 32 + row) * BC + bc) * Tn);
            uint4 v = src[ch];
            const __half* hp = reinterpret_cast<const __half*>(&v);
            int i = ch * 8;
#pragma unroll
            for (int k = 0; k < 8; k++)
                ys[i + k][row] = __half2float(hp[k]);
        }
    }
    __syncthreads();

    float Dv = *Dp;
    int lane = threadIdx.x & 31;
    int r = threadIdx.x >> 5;
    size_t base = ((size_t)b * Ln + (size_t)c * Tn + r) * Hn + ht * 32 + lane;
    if (Dv != 0.0f) {
#pragma unroll
        for (int i0 = 0; i0 < Tn; i0 += 8) {
            int i = i0 + r;
            size_t gidx = base + (size_t)i0 * Hn;
            float v = ys[i][lane] + Dv * u[gidx];
            out[gidx] = gelu_erf(v);
        }
    } else {
#pragma unroll
        for (int i0 = 0; i0 < Tn; i0 += 8) {
            int i = i0 + r;
            size_t gidx = base + (size_t)i0 * Hn;
            out[gidx] = gelu_erf(ys[i][lane]);
        }
    }
}

// =====================================================================
// launch: two staggered h-half pipelines on two streams (fork/join)
// =====================================================================
extern "C" void kernel_launch(void* const* d_in, const int* in_sizes, int n_in,
                              void* d_out, int out_size) {
    (void)in_sizes; (void)n_in; (void)out_size;
    const float* u      = (const float*)d_in[0];
    const float* log_dt = (const float*)d_in[1];
    const float* A_real = (const float*)d_in[2];
    const float* A_imag = (const float*)d_in[3];
    const float* C_real = (const float*)d_in[4];
    const float* C_imag = (const float*)d_in[5];
    const float* D      = (const float*)d_in[6];
    float* out = (float*)d_out;

    static bool init_done = false;
    static cudaStream_t s2;
    static cudaEvent_t evT, evJoin;
    if (!init_done) {
        cudaFuncSetAttribute(k_fused, cudaFuncAttributeMaxDynamicSharedMemorySize,
                             SMEM_FUSED);
        cudaStreamCreateWithFlags(&s2, cudaStreamNonBlocking);
        cudaEventCreateWithFlags(&evT, cudaEventDisableTiming);
        cudaEventCreateWithFlags(&evJoin, cudaEventDisableTiming);
        init_done = true;
    }

    // Pipeline A (h 0..511) on the launch stream
    k_transpose<<<dim3(16, Cc, Bn), 256>>>(u, 0);
    cudaEventRecord(evT, 0);                 // fork point: T_A complete
    k_fused<<<dim3(512, 2), 256, SMEM_FUSED>>>(log_dt, A_real, A_imag,
                                               C_real, C_imag, 0);
    k_final<<<dim3(16, Cc, Bn), 256>>>(u, D, out, 0);

    // Pipeline B (h 512..1023) on s2, staggered after T_A
    cudaStreamWaitEvent(s2, evT, 0);
    k_transpose<<<dim3(16, Cc, Bn), 256, 0, s2>>>(u, 16);
    k_fused<<<dim3(512, 2), 256, SMEM_FUSED, s2>>>(log_dt, A_real, A_imag,
                                                   C_real, C_imag, 512);
    k_final<<<dim3(16, Cc, Bn), 256, 0, s2>>>(u, D, out, 16);

    // join back to the launch stream
    cudaEventRecord(evJoin, s2);
    cudaStreamWaitEvent(0, evJoin, 0);
}